// round 9
// baseline (speedup 1.0000x reference)
#include <cuda_runtime.h>
#include <math.h>

#define TT    64
#define BB    2048
#define LAT   128
#define OBSD  128
#define CTRL  16
#define NMATD 16
#define HH    128
#define TM1   (TT - 1)

// ---------------- scratch (no allocation allowed) ----------------
__device__ float g_h0[BB * HH];
__device__ float g_h1[BB * HH];
__device__ float g_c[BB * HH];
__device__ float g_hbuf[BB * HH];
__device__ float g_wbuf[BB * LAT];
__device__ float g_alpha[BB * NMATD];
__device__ float g_P[BB * NMATD * LAT];         // 2048 x 2048
__device__ float g_WxP[128 * 512];              // permuted LSTM x-weights
__device__ float g_WhP[128 * 512];              // permuted LSTM h-weights
__device__ float g_bstack[512];
__device__ float g_Mbig[272 * NMATD * LAT];     // rows c in [z|u|w], cols i*128+j
__device__ float g_W2il_init[128 * 256];        // interleaved (mean,logvar) cols
__device__ float g_W2il_rec[128 * 256];
__device__ float g_b2il_init[256];
__device__ float g_b2il_rec[256];
__device__ float g_Gx[TT * BB * 512];           // batched x@WxP for all t
__device__ float g_Rxu[TM1 * BB * HH];          // [x_{t+1}|u_t]@recW1[128:]+b1
__device__ float g_alphau[TM1 * BB * NMATD];    // u_t part of alpha logits
__device__ float g_Hobs[TM1 * BB * HH];         // batched obs hidden

// ---------------- helpers ----------------
__device__ __forceinline__ float tf32r(float x) {
    unsigned u;
    asm("cvt.rna.tf32.f32 %0, %1;" : "=r"(u) : "f"(x));
    return __uint_as_float(u);
}

__device__ __forceinline__ void mma8(float (&c)[4], const float (&a)[4],
                                     const float (&b)[2]) {
    asm volatile(
        "mma.sync.aligned.m16n8k8.row.col.f32.tf32.tf32.f32 "
        "{%0,%1,%2,%3}, {%4,%5,%6,%7}, {%8,%9}, {%0,%1,%2,%3};\n"
        : "+f"(c[0]), "+f"(c[1]), "+f"(c[2]), "+f"(c[3])
        : "r"(__float_as_uint(a[0])), "r"(__float_as_uint(a[1])),
          "r"(__float_as_uint(a[2])), "r"(__float_as_uint(a[3])),
          "r"(__float_as_uint(b[0])), "r"(__float_as_uint(b[1])));
}

// ---------------- weight prep ----------------
// LSTM cols permuted: cp = (j>>3)*32 + gate*8 + (j&7); flax gate order i,f,g,o.
__global__ void build_wstack(const float* __restrict__ Wx,
                             const float* __restrict__ Wh,
                             const float* __restrict__ b) {
    int idx = blockIdx.x * blockDim.x + threadIdx.x;
    if (idx < 128 * 512) {
        int row = idx / 512, cp = idx % 512;
        int gate = (cp >> 3) & 3;
        int j = (cp >> 5) * 8 + (cp & 7);
        int orig = gate * 128 + j;
        g_WxP[idx] = Wx[row * 512 + orig];
        g_WhP[idx] = Wh[row * 512 + orig];
    }
    if (idx < 512) {
        int gate = (idx >> 3) & 3;
        int j = (idx >> 5) * 8 + (idx & 7);
        g_bstack[idx] = b[gate * 128 + j];
    }
}

__global__ void build_mbig(const float* __restrict__ A,
                           const float* __restrict__ Bm,
                           const float* __restrict__ C) {
    int idx = blockIdx.x * blockDim.x + threadIdx.x;
    if (idx >= 272 * 2048) return;
    int c = idx / 2048, n = idx % 2048;
    int i = n >> 7, j = n & 127;
    float v;
    if (c < 128)       v = A[i * 128 * 128 + j * 128 + c];
    else if (c < 144)  v = Bm[i * 128 * 16 + j * 16 + (c - 128)];
    else               v = C[i * 128 * 128 + j * 128 + (c - 144)];
    g_Mbig[idx] = v;
}

__global__ void build_w2il(const float* __restrict__ W, const float* __restrict__ b,
                           float* __restrict__ Wil, float* __restrict__ bil) {
    int idx = blockIdx.x * blockDim.x + threadIdx.x;
    if (idx < 128 * 256) {
        int k = idx / 256, cp = idx % 256;
        Wil[idx] = W[k * 256 + (cp & 1) * 128 + (cp >> 1)];
    }
    if (idx < 256) bil[idx] = b[(idx & 1) * 128 + (idx >> 1)];
}

// alphau[m,i] = sum_k us[m,k] * aW[128+k, i]
__global__ void alphau_kernel(const float* __restrict__ us,
                              const float* __restrict__ aW) {
    int m = blockIdx.x * blockDim.x + threadIdx.x;
    if (m >= TM1 * BB) return;
    float u[16];
    const float* up = us + (size_t)m * 16;
#pragma unroll
    for (int k = 0; k < 16; k++) u[k] = up[k];
#pragma unroll
    for (int i = 0; i < 16; i++) {
        float s = 0.f;
#pragma unroll
        for (int k = 0; k < 16; k++) s += u[k] * aW[(128 + k) * 16 + i];
        g_alphau[(size_t)m * 16 + i] = s;
    }
}

// ---------------- tf32 tensor GEMM, CTA 128x128, cat3 A operand ----------------
// ACT: 0 none, 1 relu, 2 gauss (W interleaved, N=256, out=mean+exp(lv/2)*eps,
// out stride 128).
template <int ACT, bool BIAS>
__global__ __launch_bounds__(256) void tmm(
    const float* __restrict__ s0, int w0,
    const float* __restrict__ s1, int w1,
    const float* __restrict__ s2, int w2,
    const float* __restrict__ W, const float* __restrict__ bias,
    const float* __restrict__ eps,
    float* __restrict__ out, int M, int N, int K) {
    __shared__ float As[16][136];
    __shared__ float Bs[16][136];
    const int tid = threadIdx.x;
    const int lane = tid & 31, warp = tid >> 5;
    const int m0 = blockIdx.x * 128, n0 = blockIdx.y * 128;
    const int wm = (warp >> 2) * 64, wn = (warp & 3) * 32;
    const int g = lane >> 2, tg = lane & 3;
    float acc[4][4][4];
#pragma unroll
    for (int i = 0; i < 4; i++)
#pragma unroll
        for (int j = 0; j < 4; j++)
#pragma unroll
            for (int q = 0; q < 4; q++) acc[i][j][q] = 0.f;

    const int nch = K >> 4;
    float4 pa[2], pb[2];

    auto gload = [&](int ch) {
        int kb = ch << 4;
        const float* sp; int sw;
        if (kb < w0)           { sp = s0 + kb;            sw = w0; }
        else if (kb < w0 + w1) { sp = s1 + (kb - w0);      sw = w1; }
        else                   { sp = s2 + (kb - w0 - w1); sw = w2; }
#pragma unroll
        for (int i = 0; i < 2; i++) {
            int idx = tid + (i << 8);
            int r = idx >> 2, c4 = (idx & 3) << 2;
            pa[i] = *(const float4*)(sp + (size_t)(m0 + r) * sw + c4);
            int br = idx >> 5, bc4 = (idx & 31) << 2;
            pb[i] = *(const float4*)(W + (size_t)(kb + br) * N + n0 + bc4);
        }
    };
    auto sstore = [&]() {
#pragma unroll
        for (int i = 0; i < 2; i++) {
            int idx = tid + (i << 8);
            int r = idx >> 2, c4 = (idx & 3) << 2;
            As[c4 + 0][r] = tf32r(pa[i].x); As[c4 + 1][r] = tf32r(pa[i].y);
            As[c4 + 2][r] = tf32r(pa[i].z); As[c4 + 3][r] = tf32r(pa[i].w);
            int br = idx >> 5, bc4 = (idx & 31) << 2;
            float4 t;
            t.x = tf32r(pb[i].x); t.y = tf32r(pb[i].y);
            t.z = tf32r(pb[i].z); t.w = tf32r(pb[i].w);
            *(float4*)&Bs[br][bc4] = t;
        }
    };

    gload(0);
    for (int ch = 0; ch < nch; ch++) {
        __syncthreads();
        sstore();
        __syncthreads();
        if (ch + 1 < nch) gload(ch + 1);
#pragma unroll
        for (int kk = 0; kk < 16; kk += 8) {
            float a[4][4], b[4][2];
#pragma unroll
            for (int mt = 0; mt < 4; mt++) {
                int r = wm + mt * 16 + g;
                a[mt][0] = As[kk + tg][r];
                a[mt][1] = As[kk + tg][r + 8];
                a[mt][2] = As[kk + tg + 4][r];
                a[mt][3] = As[kk + tg + 4][r + 8];
            }
#pragma unroll
            for (int nt = 0; nt < 4; nt++) {
                int c = wn + nt * 8 + g;
                b[nt][0] = Bs[kk + tg][c];
                b[nt][1] = Bs[kk + tg + 4][c];
            }
#pragma unroll
            for (int mt = 0; mt < 4; mt++)
#pragma unroll
                for (int nt = 0; nt < 4; nt++)
                    mma8(acc[mt][nt], a[mt], b[nt]);
        }
    }

#pragma unroll
    for (int mt = 0; mt < 4; mt++) {
#pragma unroll
        for (int nt = 0; nt < 4; nt++) {
            int r = m0 + wm + mt * 16 + g;
            int c = n0 + wn + nt * 8 + 2 * tg;
            if (ACT == 2) {
                int j = c >> 1;
                float bm = bias[c], bl = bias[c + 1];
                float mean0 = acc[mt][nt][0] + bm, lv0 = acc[mt][nt][1] + bl;
                float mean1 = acc[mt][nt][2] + bm, lv1 = acc[mt][nt][3] + bl;
                out[(size_t)r * 128 + j] =
                    mean0 + expf(0.5f * lv0) * eps[(size_t)r * 128 + j];
                out[(size_t)(r + 8) * 128 + j] =
                    mean1 + expf(0.5f * lv1) * eps[(size_t)(r + 8) * 128 + j];
            } else {
                float2 v0 = make_float2(acc[mt][nt][0], acc[mt][nt][1]);
                float2 v1 = make_float2(acc[mt][nt][2], acc[mt][nt][3]);
                if (BIAS) {
                    float bx = bias[c], by = bias[c + 1];
                    v0.x += bx; v0.y += by; v1.x += bx; v1.y += by;
                }
                if (ACT == 1) {
                    v0.x = fmaxf(v0.x, 0.f); v0.y = fmaxf(v0.y, 0.f);
                    v1.x = fmaxf(v1.x, 0.f); v1.y = fmaxf(v1.y, 0.f);
                }
                *(float2*)(out + (size_t)r * N + c) = v0;
                *(float2*)(out + (size_t)(r + 8) * N + c) = v1;
            }
        }
    }
}

// ---------------- fused tf32 LSTM step (h-part only; x-part precomputed) ----
__global__ __launch_bounds__(256) void lstm_step(
    const float* __restrict__ gx, const float* __restrict__ hin,
    float* __restrict__ c, float* __restrict__ hout) {
    __shared__ float As[16][136];
    __shared__ float Bs[16][136];
    const int tid = threadIdx.x;
    const int lane = tid & 31, warp = tid >> 5;
    const int m0 = blockIdx.x * 128, n0 = blockIdx.y * 128;
    const int wm = (warp >> 2) * 64, wn = (warp & 3) * 32;
    const int g = lane >> 2, tg = lane & 3;
    float acc[4][4][4];
#pragma unroll
    for (int i = 0; i < 4; i++)
#pragma unroll
        for (int j = 0; j < 4; j++)
#pragma unroll
            for (int q = 0; q < 4; q++) acc[i][j][q] = 0.f;

    float4 pa[2], pb[2];
    auto gload = [&](int ch) {
        int kb = ch << 4;
#pragma unroll
        for (int i = 0; i < 2; i++) {
            int idx = tid + (i << 8);
            int r = idx >> 2, c4 = (idx & 3) << 2;
            pa[i] = *(const float4*)(hin + (size_t)(m0 + r) * 128 + kb + c4);
            int br = idx >> 5, bc4 = (idx & 31) << 2;
            pb[i] = *(const float4*)(g_WhP + (size_t)(kb + br) * 512 + n0 + bc4);
        }
    };
    auto sstore = [&]() {
#pragma unroll
        for (int i = 0; i < 2; i++) {
            int idx = tid + (i << 8);
            int r = idx >> 2, c4 = (idx & 3) << 2;
            As[c4 + 0][r] = tf32r(pa[i].x); As[c4 + 1][r] = tf32r(pa[i].y);
            As[c4 + 2][r] = tf32r(pa[i].z); As[c4 + 3][r] = tf32r(pa[i].w);
            int br = idx >> 5, bc4 = (idx & 31) << 2;
            float4 t;
            t.x = tf32r(pb[i].x); t.y = tf32r(pb[i].y);
            t.z = tf32r(pb[i].z); t.w = tf32r(pb[i].w);
            *(float4*)&Bs[br][bc4] = t;
        }
    };

    gload(0);
    for (int ch = 0; ch < 8; ch++) {
        __syncthreads();
        sstore();
        __syncthreads();
        if (ch + 1 < 8) gload(ch + 1);
#pragma unroll
        for (int kk = 0; kk < 16; kk += 8) {
            float a[4][4], b[4][2];
#pragma unroll
            for (int mt = 0; mt < 4; mt++) {
                int r = wm + mt * 16 + g;
                a[mt][0] = As[kk + tg][r];
                a[mt][1] = As[kk + tg][r + 8];
                a[mt][2] = As[kk + tg + 4][r];
                a[mt][3] = As[kk + tg + 4][r + 8];
            }
#pragma unroll
            for (int nt = 0; nt < 4; nt++) {
                int cc = wn + nt * 8 + g;
                b[nt][0] = Bs[kk + tg][cc];
                b[nt][1] = Bs[kk + tg + 4][cc];
            }
#pragma unroll
            for (int mt = 0; mt < 4; mt++)
#pragma unroll
                for (int nt = 0; nt < 4; nt++)
                    mma8(acc[mt][nt], a[mt], b[nt]);
        }
    }

    const int jbase = ((n0 + wn) >> 5) * 8 + 2 * tg;
    float bs[4][2];
#pragma unroll
    for (int nt = 0; nt < 4; nt++) {
        bs[nt][0] = g_bstack[n0 + wn + nt * 8 + 2 * tg];
        bs[nt][1] = g_bstack[n0 + wn + nt * 8 + 2 * tg + 1];
    }
#pragma unroll
    for (int mt = 0; mt < 4; mt++) {
#pragma unroll
        for (int half = 0; half < 2; half++) {
            int row = m0 + wm + mt * 16 + g + half * 8;
            float2 gxv[4];
#pragma unroll
            for (int nt = 0; nt < 4; nt++)
                gxv[nt] = *(const float2*)(gx + (size_t)row * 512 + n0 + wn + nt * 8 + 2 * tg);
#pragma unroll
            for (int b = 0; b < 2; b++) {
                int q = half * 2 + b;
                float gi = acc[mt][0][q] + bs[0][b] + (b ? gxv[0].y : gxv[0].x);
                float gf = acc[mt][1][q] + bs[1][b] + (b ? gxv[1].y : gxv[1].x);
                float gg = acc[mt][2][q] + bs[2][b] + (b ? gxv[2].y : gxv[2].x);
                float go = acc[mt][3][q] + bs[3][b] + (b ? gxv[3].y : gxv[3].x);
                float si = 1.f / (1.f + expf(-gi));
                float sf = 1.f / (1.f + expf(-gf));
                float so = 1.f / (1.f + expf(-go));
                size_t idx = (size_t)row * 128 + jbase + b;
                float cn = sf * c[idx] + si * tanhf(gg);
                c[idx] = cn;
                hout[idx] = so * tanhf(cn);
            }
        }
    }
}

// ---------------- K1: fused [z-reduce] + rec1 + gauss + alpha -------------
// Grid 32 CTAs x 64 rows, 256 threads, dynamic smem.
// smem layout (floats): Zs[64*132] | Rs[64*132] | Bsm[16*136] | sl[64*16]
#define K1_SMEM_FLOATS (8448 + 8448 + 2176 + 1024)
__global__ __launch_bounds__(256) void k1_kernel(
    const float* __restrict__ Pprev,
    const float* __restrict__ alphau_t,
    const float* __restrict__ Rxu_t,
    const float* __restrict__ recW1,
    const float* __restrict__ Wil_r, const float* __restrict__ bil_r,
    const float* __restrict__ eps_t,
    const float* __restrict__ aW,
    float* __restrict__ z_io,      // zs_t : read (t==0) or write (t>0)
    float* __restrict__ wbuf,
    float* __restrict__ alphaB,    // read prev (phase0), write this (phaseC)
    int first) {
    extern __shared__ float sm[];
    float* Zs  = sm;                 // [64][132]
    float* Rs  = sm + 8448;          // [64][132]
    float* Bsm = sm + 16896;         // [16][136]
    float* sl  = sm + 19072;         // [64][16]
    const int tid = threadIdx.x;
    const int lane = tid & 31, warp = tid >> 5;
    const int m0 = blockIdx.x * 64;
    const int wm = (warp >> 2) * 32, wn = (warp & 3) * 32;
    const int g = lane >> 2, tg = lane & 3;

    // ---- phase 0: z_t (reduce from Pprev, or load for t==0) ----
    {
        int j = tid & 127, r0 = tid >> 7;
        for (int it = 0; it < 32; it++) {
            int r = r0 + it * 2;
            int b = m0 + r;
            float v;
            if (first) {
                v = z_io[(size_t)b * 128 + j];
            } else {
                const float* pb = Pprev + (size_t)b * 2048 + j;
                const float* ab = alphaB + (size_t)b * 16;
                v = 0.f;
#pragma unroll
                for (int i = 0; i < 16; i++) v += ab[i] * pb[i * 128];
                z_io[(size_t)b * 128 + j] = v;
            }
            Zs[r * 132 + j] = v;
        }
    }
    __syncthreads();

    // ---- phase C: alpha for this block's rows (uses Zs) ----
    {
        int r = tid >> 2, i0 = (tid & 3) * 4;
        float lg[4];
#pragma unroll
        for (int q = 0; q < 4; q++)
            lg[q] = alphau_t[(size_t)(m0 + r) * 16 + i0 + q];
        for (int k = 0; k < 128; k++) {
            float zv = Zs[r * 132 + k];
#pragma unroll
            for (int q = 0; q < 4; q++) lg[q] += zv * aW[k * 16 + i0 + q];
        }
#pragma unroll
        for (int q = 0; q < 4; q++) sl[r * 16 + i0 + q] = lg[q];
    }
    __syncthreads();
    {
        int r = tid >> 2, i0 = (tid & 3) * 4;
        float mx = -1e30f;
#pragma unroll
        for (int q = 0; q < 16; q++) mx = fmaxf(mx, sl[r * 16 + q]);
        float s = 0.f;
#pragma unroll
        for (int q = 0; q < 16; q++) s += expf(sl[r * 16 + q] - mx);
        float inv = 1.f / s;
#pragma unroll
        for (int q = 0; q < 4; q++)
            alphaB[(size_t)(m0 + r) * 16 + i0 + q] =
                expf(sl[r * 16 + i0 + q] - mx) * inv;
    }

    // ---- phase A: rbuf = relu(z @ recW1[0:128] + Rxu_t) ----
    {
        float acc[2][4][4];
#pragma unroll
        for (int i = 0; i < 2; i++)
#pragma unroll
            for (int j = 0; j < 4; j++)
#pragma unroll
                for (int q = 0; q < 4; q++) acc[i][j][q] = 0.f;
        float4 pb[2];
        auto gloadB = [&](int ch) {
#pragma unroll
            for (int i = 0; i < 2; i++) {
                int idx = tid + (i << 8);
                int br = idx >> 5, bc4 = (idx & 31) << 2;
                pb[i] = *(const float4*)(recW1 + (size_t)(ch * 16 + br) * 128 + bc4);
            }
        };
        auto sstoreB = [&]() {
#pragma unroll
            for (int i = 0; i < 2; i++) {
                int idx = tid + (i << 8);
                int br = idx >> 5, bc4 = (idx & 31) << 2;
                float4 t;
                t.x = tf32r(pb[i].x); t.y = tf32r(pb[i].y);
                t.z = tf32r(pb[i].z); t.w = tf32r(pb[i].w);
                *(float4*)&Bsm[br * 136 + bc4] = t;
            }
        };
        gloadB(0);
        for (int ch = 0; ch < 8; ch++) {
            __syncthreads();
            sstoreB();
            __syncthreads();
            if (ch + 1 < 8) gloadB(ch + 1);
            int kb = ch << 4;
#pragma unroll
            for (int kk = 0; kk < 16; kk += 8) {
                float a[2][4], b[4][2];
#pragma unroll
                for (int mt = 0; mt < 2; mt++) {
                    int r = wm + mt * 16 + g;
                    a[mt][0] = tf32r(Zs[r * 132 + kb + kk + tg]);
                    a[mt][1] = tf32r(Zs[(r + 8) * 132 + kb + kk + tg]);
                    a[mt][2] = tf32r(Zs[r * 132 + kb + kk + tg + 4]);
                    a[mt][3] = tf32r(Zs[(r + 8) * 132 + kb + kk + tg + 4]);
                }
#pragma unroll
                for (int nt = 0; nt < 4; nt++) {
                    int c = wn + nt * 8 + g;
                    b[nt][0] = Bsm[(kk + tg) * 136 + c];
                    b[nt][1] = Bsm[(kk + tg + 4) * 136 + c];
                }
#pragma unroll
                for (int mt = 0; mt < 2; mt++)
#pragma unroll
                    for (int nt = 0; nt < 4; nt++)
                        mma8(acc[mt][nt], a[mt], b[nt]);
            }
        }
        __syncthreads();
#pragma unroll
        for (int mt = 0; mt < 2; mt++) {
#pragma unroll
            for (int nt = 0; nt < 4; nt++) {
                int r = wm + mt * 16 + g;
                int c = wn + nt * 8 + 2 * tg;
                float2 x0 = *(const float2*)(Rxu_t + (size_t)(m0 + r) * 128 + c);
                float2 x1 = *(const float2*)(Rxu_t + (size_t)(m0 + r + 8) * 128 + c);
                Rs[r * 132 + c]           = fmaxf(acc[mt][nt][0] + x0.x, 0.f);
                Rs[r * 132 + c + 1]       = fmaxf(acc[mt][nt][1] + x0.y, 0.f);
                Rs[(r + 8) * 132 + c]     = fmaxf(acc[mt][nt][2] + x1.x, 0.f);
                Rs[(r + 8) * 132 + c + 1] = fmaxf(acc[mt][nt][3] + x1.y, 0.f);
            }
        }
    }
    __syncthreads();

    // ---- phase B: w = gauss(rbuf @ Wil_r + bil_r) over two n-halves ----
    for (int half = 0; half < 2; half++) {
        float acc[2][4][4];
#pragma unroll
        for (int i = 0; i < 2; i++)
#pragma unroll
            for (int j = 0; j < 4; j++)
#pragma unroll
                for (int q = 0; q < 4; q++) acc[i][j][q] = 0.f;
        float4 pb[2];
        auto gloadB = [&](int ch) {
#pragma unroll
            for (int i = 0; i < 2; i++) {
                int idx = tid + (i << 8);
                int br = idx >> 5, bc4 = (idx & 31) << 2;
                pb[i] = *(const float4*)(Wil_r + (size_t)(ch * 16 + br) * 256 +
                                         half * 128 + bc4);
            }
        };
        auto sstoreB = [&]() {
#pragma unroll
            for (int i = 0; i < 2; i++) {
                int idx = tid + (i << 8);
                int br = idx >> 5, bc4 = (idx & 31) << 2;
                float4 t;
                t.x = tf32r(pb[i].x); t.y = tf32r(pb[i].y);
                t.z = tf32r(pb[i].z); t.w = tf32r(pb[i].w);
                *(float4*)&Bsm[br * 136 + bc4] = t;
            }
        };
        gloadB(0);
        for (int ch = 0; ch < 8; ch++) {
            __syncthreads();
            sstoreB();
            __syncthreads();
            if (ch + 1 < 8) gloadB(ch + 1);
            int kb = ch << 4;
#pragma unroll
            for (int kk = 0; kk < 16; kk += 8) {
                float a[2][4], b[4][2];
#pragma unroll
                for (int mt = 0; mt < 2; mt++) {
                    int r = wm + mt * 16 + g;
                    a[mt][0] = tf32r(Rs[r * 132 + kb + kk + tg]);
                    a[mt][1] = tf32r(Rs[(r + 8) * 132 + kb + kk + tg]);
                    a[mt][2] = tf32r(Rs[r * 132 + kb + kk + tg + 4]);
                    a[mt][3] = tf32r(Rs[(r + 8) * 132 + kb + kk + tg + 4]);
                }
#pragma unroll
                for (int nt = 0; nt < 4; nt++) {
                    int c = wn + nt * 8 + g;
                    b[nt][0] = Bsm[(kk + tg) * 136 + c];
                    b[nt][1] = Bsm[(kk + tg + 4) * 136 + c];
                }
#pragma unroll
                for (int mt = 0; mt < 2; mt++)
#pragma unroll
                    for (int nt = 0; nt < 4; nt++)
                        mma8(acc[mt][nt], a[mt], b[nt]);
            }
        }
        __syncthreads();
#pragma unroll
        for (int mt = 0; mt < 2; mt++) {
#pragma unroll
            for (int nt = 0; nt < 4; nt++) {
                int r = m0 + wm + mt * 16 + g;
                int gc = half * 128 + wn + nt * 8 + 2 * tg;
                int j = gc >> 1;
                float bm = bil_r[gc], bl = bil_r[gc + 1];
                float mean0 = acc[mt][nt][0] + bm, lv0 = acc[mt][nt][1] + bl;
                float mean1 = acc[mt][nt][2] + bm, lv1 = acc[mt][nt][3] + bl;
                wbuf[(size_t)r * 128 + j] =
                    mean0 + expf(0.5f * lv0) * eps_t[(size_t)r * 128 + j];
                wbuf[(size_t)(r + 8) * 128 + j] =
                    mean1 + expf(0.5f * lv1) * eps_t[(size_t)(r + 8) * 128 + j];
            }
        }
    }
}

// ---------------- final z_63 = alpha-weighted reduce of P_62 --------------
__global__ __launch_bounds__(256) void zfinal(
    const float* __restrict__ P, const float* __restrict__ alphaB,
    float* __restrict__ znext) {
    int idx = blockIdx.x * 256 + threadIdx.x;
    int b = idx >> 7, j = idx & 127;
    const float* pb = P + (size_t)b * 2048 + j;
    const float* ab = alphaB + (size_t)b * 16;
    float s = 0.f;
#pragma unroll
    for (int i = 0; i < 16; i++) s += ab[i] * pb[i * 128];
    znext[idx] = s;
}

// ---------------- host orchestration ----------------
extern "C" void kernel_launch(void* const* d_in, const int* in_sizes, int n_in,
                              void* d_out, int out_size) {
    const float* xs      = (const float*)d_in[0];
    const float* us      = (const float*)d_in[1];
    const float* eps1    = (const float*)d_in[2];
    const float* eps     = (const float*)d_in[3];
    const float* lstm_Wx = (const float*)d_in[4];
    const float* lstm_Wh = (const float*)d_in[5];
    const float* lstm_b  = (const float*)d_in[6];
    const float* init_W1 = (const float*)d_in[7];
    const float* init_b1 = (const float*)d_in[8];
    const float* init_W2 = (const float*)d_in[9];
    const float* init_b2 = (const float*)d_in[10];
    const float* trans_W1= (const float*)d_in[11];
    const float* trans_b1= (const float*)d_in[12];
    const float* trans_W2= (const float*)d_in[13];
    const float* trans_b2= (const float*)d_in[14];
    const float* obs_W1  = (const float*)d_in[15];
    const float* obs_b1  = (const float*)d_in[16];
    const float* obs_W2  = (const float*)d_in[17];
    const float* obs_b2  = (const float*)d_in[18];
    const float* rec_W1  = (const float*)d_in[19];
    const float* rec_b1  = (const float*)d_in[20];
    const float* rec_W2  = (const float*)d_in[21];
    const float* rec_b2  = (const float*)d_in[22];
    const float* alpha_W = (const float*)d_in[23];
    const float* Abank   = (const float*)d_in[24];
    const float* Bbank   = (const float*)d_in[25];
    const float* Cbank   = (const float*)d_in[26];

    float *h0, *h1, *c, *hbuf, *wbuf, *alphaB, *P;
    float *Wil_i, *Wil_r, *bil_i, *bil_r, *Mbig, *Gx, *Rxu, *alphau, *Hobs, *WxP;
    cudaGetSymbolAddress((void**)&h0, g_h0);
    cudaGetSymbolAddress((void**)&h1, g_h1);
    cudaGetSymbolAddress((void**)&c, g_c);
    cudaGetSymbolAddress((void**)&hbuf, g_hbuf);
    cudaGetSymbolAddress((void**)&wbuf, g_wbuf);
    cudaGetSymbolAddress((void**)&alphaB, g_alpha);
    cudaGetSymbolAddress((void**)&P, g_P);
    cudaGetSymbolAddress((void**)&Mbig, g_Mbig);
    cudaGetSymbolAddress((void**)&Wil_i, g_W2il_init);
    cudaGetSymbolAddress((void**)&Wil_r, g_W2il_rec);
    cudaGetSymbolAddress((void**)&bil_i, g_b2il_init);
    cudaGetSymbolAddress((void**)&bil_r, g_b2il_rec);
    cudaGetSymbolAddress((void**)&Gx, g_Gx);
    cudaGetSymbolAddress((void**)&Rxu, g_Rxu);
    cudaGetSymbolAddress((void**)&alphau, g_alphau);
    cudaGetSymbolAddress((void**)&Hobs, g_Hobs);
    cudaGetSymbolAddress((void**)&WxP, g_WxP);

    static int k1_attr_done = 0;
    if (!k1_attr_done) {
        cudaFuncSetAttribute(k1_kernel, cudaFuncAttributeMaxDynamicSharedMemorySize,
                             K1_SMEM_FLOATS * 4);
        k1_attr_done = 1;
    }

    cudaMemsetAsync(h0, 0, sizeof(float) * BB * HH);
    cudaMemsetAsync(c, 0, sizeof(float) * BB * HH);

    build_wstack<<<(128 * 512 + 255) / 256, 256>>>(lstm_Wx, lstm_Wh, lstm_b);
    build_mbig<<<(272 * 2048 + 255) / 256, 256>>>(Abank, Bbank, Cbank);
    build_w2il<<<(128 * 256 + 255) / 256, 256>>>(init_W2, init_b2, Wil_i, bil_i);
    build_w2il<<<(128 * 256 + 255) / 256, 256>>>(rec_W2, rec_b2, Wil_r, bil_r);
    alphau_kernel<<<(TM1 * BB + 255) / 256, 256>>>(us, alpha_W);

    // batched x-part of LSTM gates for all t
    tmm<0, false><<<dim3(TT * BB / 128, 4), 256>>>(
        xs, 128, nullptr, 0, nullptr, 0, WxP, nullptr, nullptr,
        Gx, TT * BB, 512, 128);
    // batched [x_{t+1}|u_t] part of recognition stage 1 (+bias)
    tmm<0, true><<<dim3(TM1 * BB / 128, 1), 256>>>(
        xs + (size_t)BB * OBSD, 128, us, 16, nullptr, 0,
        rec_W1 + 128 * 128, rec_b1, nullptr, Rxu, TM1 * BB, 128, 144);

    // LSTM over T (ping-pong h)
    dim3 gLSTM(BB / 128, 4);
    for (int t = 0; t < TT; t++) {
        const float* hin = (t & 1) ? h1 : h0;
        float* hout      = (t & 1) ? h0 : h1;
        lstm_step<<<gLSTM, 256>>>(Gx + (size_t)t * BB * 512, hin, c, hout);
    }
    float* hfin = h0;  // t=63 (odd) wrote h0

    float* zs   = (float*)d_out;
    float* xrec = zs + (size_t)TT * BB * LAT;

    dim3 g1(BB / 128, 1), g2(BB / 128, 2), gMix(BB / 128, 16);
    // init network -> z_0 in zs
    tmm<1, true><<<g1, 256>>>(hfin, 128, nullptr, 0, nullptr, 0,
                              init_W1, init_b1, nullptr, hbuf, BB, 128, 128);
    tmm<2, true><<<g2, 256>>>(hbuf, 128, nullptr, 0, nullptr, 0,
                              Wil_i, bil_i, eps1, wbuf, BB, 256, 128);
    tmm<1, true><<<g1, 256>>>(wbuf, 128, nullptr, 0, nullptr, 0,
                              trans_W1, trans_b1, nullptr, hbuf, BB, 128, 128);
    tmm<0, true><<<g1, 256>>>(hbuf, 128, nullptr, 0, nullptr, 0,
                              trans_W2, trans_b2, nullptr, zs, BB, 128, 128);

    // scan: 2 kernels per step
    for (int t = 0; t < TM1; t++) {
        float* z = zs + (size_t)t * BB * LAT;
        k1_kernel<<<32, 256, K1_SMEM_FLOATS * 4>>>(
            P, alphau + (size_t)t * BB * NMATD,
            Rxu + (size_t)t * BB * HH, rec_W1,
            Wil_r, bil_r, eps + (size_t)t * BB * LAT, alpha_W,
            z, wbuf, alphaB, t == 0);
        tmm<0, false><<<gMix, 256>>>(z, 128, us + (size_t)t * BB * CTRL, 16,
                                     wbuf, 128, Mbig, nullptr, nullptr,
                                     P, BB, 2048, 272);
    }
    zfinal<<<BB * 128 / 256, 256>>>(P, alphaB, zs + (size_t)(TT - 1) * BB * LAT);

    // batched observation network over all z_0..z_62
    tmm<1, true><<<dim3(TM1 * BB / 128, 1), 256>>>(
        zs, 128, nullptr, 0, nullptr, 0, obs_W1, obs_b1, nullptr,
        Hobs, TM1 * BB, 128, 128);
    tmm<0, true><<<dim3(TM1 * BB / 128, 1), 256>>>(
        Hobs, 128, nullptr, 0, nullptr, 0, obs_W2, obs_b2, nullptr,
        xrec, TM1 * BB, 128, 128);
}

// round 10
// speedup vs baseline: 1.1801x; 1.1801x over previous
#include <cuda_runtime.h>
#include <math.h>

#define TT    64
#define BB    2048
#define LAT   128
#define OBSD  128
#define CTRL  16
#define NMATD 16
#define HH    128
#define TM1   (TT - 1)

// ---------------- scratch (no allocation allowed) ----------------
__device__ float g_h0[BB * HH];
__device__ float g_h1[BB * HH];
__device__ float g_c[BB * HH];
__device__ float g_hbuf[BB * HH];
__device__ float g_wbuf[BB * LAT];
__device__ float g_alpha[BB * NMATD];
__device__ float g_P[BB * NMATD * LAT];         // 2048 x 2048
__device__ float g_WxP[128 * 512];              // permuted LSTM x-weights
__device__ float g_WhP[128 * 512];              // permuted LSTM h-weights
__device__ float g_bstack[512];
__device__ float g_Mbig[272 * NMATD * LAT];     // rows c in [z|u|w], cols i*128+j
__device__ float g_W2il_init[128 * 256];        // interleaved (mean,logvar) cols
__device__ float g_W2il_rec[128 * 256];
__device__ float g_b2il_init[256];
__device__ float g_b2il_rec[256];
__device__ float g_Gx[TT * BB * 512];           // batched x@WxP for all t
__device__ float g_Rxu[TM1 * BB * HH];          // [x_{t+1}|u_t]@recW1[128:]+b1
__device__ float g_alphau[TM1 * BB * NMATD];    // u_t part of alpha logits
__device__ float g_Hobs[TM1 * BB * HH];         // batched obs hidden

// ---------------- helpers ----------------
__device__ __forceinline__ float tf32r(float x) {
    unsigned u;
    asm("cvt.rna.tf32.f32 %0, %1;" : "=r"(u) : "f"(x));
    return __uint_as_float(u);
}

__device__ __forceinline__ void mma8(float (&c)[4], const float (&a)[4],
                                     const float (&b)[2]) {
    asm volatile(
        "mma.sync.aligned.m16n8k8.row.col.f32.tf32.tf32.f32 "
        "{%0,%1,%2,%3}, {%4,%5,%6,%7}, {%8,%9}, {%0,%1,%2,%3};\n"
        : "+f"(c[0]), "+f"(c[1]), "+f"(c[2]), "+f"(c[3])
        : "r"(__float_as_uint(a[0])), "r"(__float_as_uint(a[1])),
          "r"(__float_as_uint(a[2])), "r"(__float_as_uint(a[3])),
          "r"(__float_as_uint(b[0])), "r"(__float_as_uint(b[1])));
}

// ---------------- weight prep ----------------
__global__ void build_wstack(const float* __restrict__ Wx,
                             const float* __restrict__ Wh,
                             const float* __restrict__ b) {
    int idx = blockIdx.x * blockDim.x + threadIdx.x;
    if (idx < 128 * 512) {
        int row = idx / 512, cp = idx % 512;
        int gate = (cp >> 3) & 3;
        int j = (cp >> 5) * 8 + (cp & 7);
        int orig = gate * 128 + j;
        g_WxP[idx] = Wx[row * 512 + orig];
        g_WhP[idx] = Wh[row * 512 + orig];
    }
    if (idx < 512) {
        int gate = (idx >> 3) & 3;
        int j = (idx >> 5) * 8 + (idx & 7);
        g_bstack[idx] = b[gate * 128 + j];
    }
}

__global__ void build_mbig(const float* __restrict__ A,
                           const float* __restrict__ Bm,
                           const float* __restrict__ C) {
    int idx = blockIdx.x * blockDim.x + threadIdx.x;
    if (idx >= 272 * 2048) return;
    int c = idx / 2048, n = idx % 2048;
    int i = n >> 7, j = n & 127;
    float v;
    if (c < 128)       v = A[i * 128 * 128 + j * 128 + c];
    else if (c < 144)  v = Bm[i * 128 * 16 + j * 16 + (c - 128)];
    else               v = C[i * 128 * 128 + j * 128 + (c - 144)];
    g_Mbig[idx] = v;
}

__global__ void build_w2il(const float* __restrict__ W, const float* __restrict__ b,
                           float* __restrict__ Wil, float* __restrict__ bil) {
    int idx = blockIdx.x * blockDim.x + threadIdx.x;
    if (idx < 128 * 256) {
        int k = idx / 256, cp = idx % 256;
        Wil[idx] = W[k * 256 + (cp & 1) * 128 + (cp >> 1)];
    }
    if (idx < 256) bil[idx] = b[(idx & 1) * 128 + (idx >> 1)];
}

__global__ void alphau_kernel(const float* __restrict__ us,
                              const float* __restrict__ aW) {
    int m = blockIdx.x * blockDim.x + threadIdx.x;
    if (m >= TM1 * BB) return;
    float u[16];
    const float* up = us + (size_t)m * 16;
#pragma unroll
    for (int k = 0; k < 16; k++) u[k] = up[k];
#pragma unroll
    for (int i = 0; i < 16; i++) {
        float s = 0.f;
#pragma unroll
        for (int k = 0; k < 16; k++) s += u[k] * aW[(128 + k) * 16 + i];
        g_alphau[(size_t)m * 16 + i] = s;
    }
}

// ---------------- tf32 tensor GEMM, CTA 128x128, cat3 A operand ----------------
// ACT: 0 none, 1 relu, 2 gauss (W interleaved, N=256, out=mean+exp(lv/2)*eps,
// out stride 128).
template <int ACT, bool BIAS>
__global__ __launch_bounds__(256) void tmm(
    const float* __restrict__ s0, int w0,
    const float* __restrict__ s1, int w1,
    const float* __restrict__ s2, int w2,
    const float* __restrict__ W, const float* __restrict__ bias,
    const float* __restrict__ eps,
    float* __restrict__ out, int M, int N, int K) {
    __shared__ float As[16][136];
    __shared__ float Bs[16][136];
    const int tid = threadIdx.x;
    const int lane = tid & 31, warp = tid >> 5;
    const int m0 = blockIdx.x * 128, n0 = blockIdx.y * 128;
    const int wm = (warp >> 2) * 64, wn = (warp & 3) * 32;
    const int g = lane >> 2, tg = lane & 3;
    float acc[4][4][4];
#pragma unroll
    for (int i = 0; i < 4; i++)
#pragma unroll
        for (int j = 0; j < 4; j++)
#pragma unroll
            for (int q = 0; q < 4; q++) acc[i][j][q] = 0.f;

    const int nch = K >> 4;
    float4 pa[2], pb[2];

    auto gload = [&](int ch) {
        int kb = ch << 4;
        const float* sp; int sw;
        if (kb < w0)           { sp = s0 + kb;            sw = w0; }
        else if (kb < w0 + w1) { sp = s1 + (kb - w0);      sw = w1; }
        else                   { sp = s2 + (kb - w0 - w1); sw = w2; }
#pragma unroll
        for (int i = 0; i < 2; i++) {
            int idx = tid + (i << 8);
            int r = idx >> 2, c4 = (idx & 3) << 2;
            pa[i] = *(const float4*)(sp + (size_t)(m0 + r) * sw + c4);
            int br = idx >> 5, bc4 = (idx & 31) << 2;
            pb[i] = *(const float4*)(W + (size_t)(kb + br) * N + n0 + bc4);
        }
    };
    auto sstore = [&]() {
#pragma unroll
        for (int i = 0; i < 2; i++) {
            int idx = tid + (i << 8);
            int r = idx >> 2, c4 = (idx & 3) << 2;
            As[c4 + 0][r] = tf32r(pa[i].x); As[c4 + 1][r] = tf32r(pa[i].y);
            As[c4 + 2][r] = tf32r(pa[i].z); As[c4 + 3][r] = tf32r(pa[i].w);
            int br = idx >> 5, bc4 = (idx & 31) << 2;
            float4 t;
            t.x = tf32r(pb[i].x); t.y = tf32r(pb[i].y);
            t.z = tf32r(pb[i].z); t.w = tf32r(pb[i].w);
            *(float4*)&Bs[br][bc4] = t;
        }
    };

    gload(0);
    for (int ch = 0; ch < nch; ch++) {
        __syncthreads();
        sstore();
        __syncthreads();
        if (ch + 1 < nch) gload(ch + 1);
#pragma unroll
        for (int kk = 0; kk < 16; kk += 8) {
            float a[4][4], b[4][2];
#pragma unroll
            for (int mt = 0; mt < 4; mt++) {
                int r = wm + mt * 16 + g;
                a[mt][0] = As[kk + tg][r];
                a[mt][1] = As[kk + tg][r + 8];
                a[mt][2] = As[kk + tg + 4][r];
                a[mt][3] = As[kk + tg + 4][r + 8];
            }
#pragma unroll
            for (int nt = 0; nt < 4; nt++) {
                int c = wn + nt * 8 + g;
                b[nt][0] = Bs[kk + tg][c];
                b[nt][1] = Bs[kk + tg + 4][c];
            }
#pragma unroll
            for (int mt = 0; mt < 4; mt++)
#pragma unroll
                for (int nt = 0; nt < 4; nt++)
                    mma8(acc[mt][nt], a[mt], b[nt]);
        }
    }

#pragma unroll
    for (int mt = 0; mt < 4; mt++) {
#pragma unroll
        for (int nt = 0; nt < 4; nt++) {
            int r = m0 + wm + mt * 16 + g;
            int c = n0 + wn + nt * 8 + 2 * tg;
            if (ACT == 2) {
                int j = c >> 1;
                float bm = bias[c], bl = bias[c + 1];
                float mean0 = acc[mt][nt][0] + bm, lv0 = acc[mt][nt][1] + bl;
                float mean1 = acc[mt][nt][2] + bm, lv1 = acc[mt][nt][3] + bl;
                out[(size_t)r * 128 + j] =
                    mean0 + expf(0.5f * lv0) * eps[(size_t)r * 128 + j];
                out[(size_t)(r + 8) * 128 + j] =
                    mean1 + expf(0.5f * lv1) * eps[(size_t)(r + 8) * 128 + j];
            } else {
                float2 v0 = make_float2(acc[mt][nt][0], acc[mt][nt][1]);
                float2 v1 = make_float2(acc[mt][nt][2], acc[mt][nt][3]);
                if (BIAS) {
                    float bx = bias[c], by = bias[c + 1];
                    v0.x += bx; v0.y += by; v1.x += bx; v1.y += by;
                }
                if (ACT == 1) {
                    v0.x = fmaxf(v0.x, 0.f); v0.y = fmaxf(v0.y, 0.f);
                    v1.x = fmaxf(v1.x, 0.f); v1.y = fmaxf(v1.y, 0.f);
                }
                *(float2*)(out + (size_t)r * N + c) = v0;
                *(float2*)(out + (size_t)(r + 8) * N + c) = v1;
            }
        }
    }
}

// ---------------- fused tf32 LSTM step (h-part only; x-part precomputed) ----
__global__ __launch_bounds__(256) void lstm_step(
    const float* __restrict__ gx, const float* __restrict__ hin,
    float* __restrict__ c, float* __restrict__ hout) {
    __shared__ float As[16][136];
    __shared__ float Bs[16][136];
    const int tid = threadIdx.x;
    const int lane = tid & 31, warp = tid >> 5;
    const int m0 = blockIdx.x * 128, n0 = blockIdx.y * 128;
    const int wm = (warp >> 2) * 64, wn = (warp & 3) * 32;
    const int g = lane >> 2, tg = lane & 3;
    float acc[4][4][4];
#pragma unroll
    for (int i = 0; i < 4; i++)
#pragma unroll
        for (int j = 0; j < 4; j++)
#pragma unroll
            for (int q = 0; q < 4; q++) acc[i][j][q] = 0.f;

    float4 pa[2], pb[2];
    auto gload = [&](int ch) {
        int kb = ch << 4;
#pragma unroll
        for (int i = 0; i < 2; i++) {
            int idx = tid + (i << 8);
            int r = idx >> 2, c4 = (idx & 3) << 2;
            pa[i] = *(const float4*)(hin + (size_t)(m0 + r) * 128 + kb + c4);
            int br = idx >> 5, bc4 = (idx & 31) << 2;
            pb[i] = *(const float4*)(g_WhP + (size_t)(kb + br) * 512 + n0 + bc4);
        }
    };
    auto sstore = [&]() {
#pragma unroll
        for (int i = 0; i < 2; i++) {
            int idx = tid + (i << 8);
            int r = idx >> 2, c4 = (idx & 3) << 2;
            As[c4 + 0][r] = tf32r(pa[i].x); As[c4 + 1][r] = tf32r(pa[i].y);
            As[c4 + 2][r] = tf32r(pa[i].z); As[c4 + 3][r] = tf32r(pa[i].w);
            int br = idx >> 5, bc4 = (idx & 31) << 2;
            float4 t;
            t.x = tf32r(pb[i].x); t.y = tf32r(pb[i].y);
            t.z = tf32r(pb[i].z); t.w = tf32r(pb[i].w);
            *(float4*)&Bs[br][bc4] = t;
        }
    };

    gload(0);
    for (int ch = 0; ch < 8; ch++) {
        __syncthreads();
        sstore();
        __syncthreads();
        if (ch + 1 < 8) gload(ch + 1);
#pragma unroll
        for (int kk = 0; kk < 16; kk += 8) {
            float a[4][4], b[4][2];
#pragma unroll
            for (int mt = 0; mt < 4; mt++) {
                int r = wm + mt * 16 + g;
                a[mt][0] = As[kk + tg][r];
                a[mt][1] = As[kk + tg][r + 8];
                a[mt][2] = As[kk + tg + 4][r];
                a[mt][3] = As[kk + tg + 4][r + 8];
            }
#pragma unroll
            for (int nt = 0; nt < 4; nt++) {
                int cc = wn + nt * 8 + g;
                b[nt][0] = Bs[kk + tg][cc];
                b[nt][1] = Bs[kk + tg + 4][cc];
            }
#pragma unroll
            for (int mt = 0; mt < 4; mt++)
#pragma unroll
                for (int nt = 0; nt < 4; nt++)
                    mma8(acc[mt][nt], a[mt], b[nt]);
        }
    }

    const int jbase = ((n0 + wn) >> 5) * 8 + 2 * tg;
    float bs[4][2];
#pragma unroll
    for (int nt = 0; nt < 4; nt++) {
        bs[nt][0] = g_bstack[n0 + wn + nt * 8 + 2 * tg];
        bs[nt][1] = g_bstack[n0 + wn + nt * 8 + 2 * tg + 1];
    }
#pragma unroll
    for (int mt = 0; mt < 4; mt++) {
#pragma unroll
        for (int half = 0; half < 2; half++) {
            int row = m0 + wm + mt * 16 + g + half * 8;
            float2 gxv[4];
#pragma unroll
            for (int nt = 0; nt < 4; nt++)
                gxv[nt] = *(const float2*)(gx + (size_t)row * 512 + n0 + wn + nt * 8 + 2 * tg);
#pragma unroll
            for (int b = 0; b < 2; b++) {
                int q = half * 2 + b;
                float gi = acc[mt][0][q] + bs[0][b] + (b ? gxv[0].y : gxv[0].x);
                float gf = acc[mt][1][q] + bs[1][b] + (b ? gxv[1].y : gxv[1].x);
                float gg = acc[mt][2][q] + bs[2][b] + (b ? gxv[2].y : gxv[2].x);
                float go = acc[mt][3][q] + bs[3][b] + (b ? gxv[3].y : gxv[3].x);
                float si = 1.f / (1.f + expf(-gi));
                float sf = 1.f / (1.f + expf(-gf));
                float so = 1.f / (1.f + expf(-go));
                size_t idx = (size_t)row * 128 + jbase + b;
                float cn = sf * c[idx] + si * tanhf(gg);
                c[idx] = cn;
                hout[idx] = so * tanhf(cn);
            }
        }
    }
}

// ---------------- recgauss: fused rec stage1 + gauss, 64-row tiles ---------
// smem: Zs[64*132] | Rs[64*132] | Bsm[16*136]
#define RG_SMEM_FLOATS (8448 + 8448 + 2176)
__global__ __launch_bounds__(256) void recgauss(
    const float* __restrict__ z,
    const float* __restrict__ Rxu_t,
    const float* __restrict__ recW1,
    const float* __restrict__ Wil_r, const float* __restrict__ bil_r,
    const float* __restrict__ eps_t,
    float* __restrict__ wbuf) {
    extern __shared__ float sm[];
    float* Zs  = sm;                 // [64][132]
    float* Rs  = sm + 8448;          // [64][132]
    float* Bsm = sm + 16896;         // [16][136]
    const int tid = threadIdx.x;
    const int lane = tid & 31, warp = tid >> 5;
    const int m0 = blockIdx.x * 64;
    const int wm = (warp >> 2) * 32, wn = (warp & 3) * 32;
    const int g = lane >> 2, tg = lane & 3;

    // load z tile (64 x 128)
#pragma unroll
    for (int i = 0; i < 8; i++) {
        int fidx = tid + i * 256;
        int r = fidx >> 5, c4 = (fidx & 31) << 2;
        float4 v = *(const float4*)(z + (size_t)(m0 + r) * 128 + c4);
        *(float4*)&Zs[r * 132 + c4] = v;
    }
    __syncthreads();

    // ---- phase A: Rs = relu(z @ recW1[0:128] + Rxu_t) ----
    {
        float acc[2][4][4];
#pragma unroll
        for (int i = 0; i < 2; i++)
#pragma unroll
            for (int j = 0; j < 4; j++)
#pragma unroll
                for (int q = 0; q < 4; q++) acc[i][j][q] = 0.f;
        float4 pb[2];
        auto gloadB = [&](int ch) {
#pragma unroll
            for (int i = 0; i < 2; i++) {
                int idx = tid + (i << 8);
                int br = idx >> 5, bc4 = (idx & 31) << 2;
                pb[i] = *(const float4*)(recW1 + (size_t)(ch * 16 + br) * 128 + bc4);
            }
        };
        auto sstoreB = [&]() {
#pragma unroll
            for (int i = 0; i < 2; i++) {
                int idx = tid + (i << 8);
                int br = idx >> 5, bc4 = (idx & 31) << 2;
                float4 t;
                t.x = tf32r(pb[i].x); t.y = tf32r(pb[i].y);
                t.z = tf32r(pb[i].z); t.w = tf32r(pb[i].w);
                *(float4*)&Bsm[br * 136 + bc4] = t;
            }
        };
        gloadB(0);
        for (int ch = 0; ch < 8; ch++) {
            __syncthreads();
            sstoreB();
            __syncthreads();
            if (ch + 1 < 8) gloadB(ch + 1);
            int kb = ch << 4;
#pragma unroll
            for (int kk = 0; kk < 16; kk += 8) {
                float a[2][4], b[4][2];
#pragma unroll
                for (int mt = 0; mt < 2; mt++) {
                    int r = wm + mt * 16 + g;
                    a[mt][0] = tf32r(Zs[r * 132 + kb + kk + tg]);
                    a[mt][1] = tf32r(Zs[(r + 8) * 132 + kb + kk + tg]);
                    a[mt][2] = tf32r(Zs[r * 132 + kb + kk + tg + 4]);
                    a[mt][3] = tf32r(Zs[(r + 8) * 132 + kb + kk + tg + 4]);
                }
#pragma unroll
                for (int nt = 0; nt < 4; nt++) {
                    int c = wn + nt * 8 + g;
                    b[nt][0] = Bsm[(kk + tg) * 136 + c];
                    b[nt][1] = Bsm[(kk + tg + 4) * 136 + c];
                }
#pragma unroll
                for (int mt = 0; mt < 2; mt++)
#pragma unroll
                    for (int nt = 0; nt < 4; nt++)
                        mma8(acc[mt][nt], a[mt], b[nt]);
            }
        }
        __syncthreads();
#pragma unroll
        for (int mt = 0; mt < 2; mt++) {
#pragma unroll
            for (int nt = 0; nt < 4; nt++) {
                int r = wm + mt * 16 + g;
                int c = wn + nt * 8 + 2 * tg;
                float2 x0 = *(const float2*)(Rxu_t + (size_t)(m0 + r) * 128 + c);
                float2 x1 = *(const float2*)(Rxu_t + (size_t)(m0 + r + 8) * 128 + c);
                Rs[r * 132 + c]           = fmaxf(acc[mt][nt][0] + x0.x, 0.f);
                Rs[r * 132 + c + 1]       = fmaxf(acc[mt][nt][1] + x0.y, 0.f);
                Rs[(r + 8) * 132 + c]     = fmaxf(acc[mt][nt][2] + x1.x, 0.f);
                Rs[(r + 8) * 132 + c + 1] = fmaxf(acc[mt][nt][3] + x1.y, 0.f);
            }
        }
    }
    __syncthreads();

    // ---- phase B: wbuf = gauss(Rs @ Wil_r + bil_r), two n-halves ----
    for (int half = 0; half < 2; half++) {
        float acc[2][4][4];
#pragma unroll
        for (int i = 0; i < 2; i++)
#pragma unroll
            for (int j = 0; j < 4; j++)
#pragma unroll
                for (int q = 0; q < 4; q++) acc[i][j][q] = 0.f;
        float4 pb[2];
        auto gloadB = [&](int ch) {
#pragma unroll
            for (int i = 0; i < 2; i++) {
                int idx = tid + (i << 8);
                int br = idx >> 5, bc4 = (idx & 31) << 2;
                pb[i] = *(const float4*)(Wil_r + (size_t)(ch * 16 + br) * 256 +
                                         half * 128 + bc4);
            }
        };
        auto sstoreB = [&]() {
#pragma unroll
            for (int i = 0; i < 2; i++) {
                int idx = tid + (i << 8);
                int br = idx >> 5, bc4 = (idx & 31) << 2;
                float4 t;
                t.x = tf32r(pb[i].x); t.y = tf32r(pb[i].y);
                t.z = tf32r(pb[i].z); t.w = tf32r(pb[i].w);
                *(float4*)&Bsm[br * 136 + bc4] = t;
            }
        };
        gloadB(0);
        for (int ch = 0; ch < 8; ch++) {
            __syncthreads();
            sstoreB();
            __syncthreads();
            if (ch + 1 < 8) gloadB(ch + 1);
            int kb = ch << 4;
#pragma unroll
            for (int kk = 0; kk < 16; kk += 8) {
                float a[2][4], b[4][2];
#pragma unroll
                for (int mt = 0; mt < 2; mt++) {
                    int r = wm + mt * 16 + g;
                    a[mt][0] = tf32r(Rs[r * 132 + kb + kk + tg]);
                    a[mt][1] = tf32r(Rs[(r + 8) * 132 + kb + kk + tg]);
                    a[mt][2] = tf32r(Rs[r * 132 + kb + kk + tg + 4]);
                    a[mt][3] = tf32r(Rs[(r + 8) * 132 + kb + kk + tg + 4]);
                }
#pragma unroll
                for (int nt = 0; nt < 4; nt++) {
                    int c = wn + nt * 8 + g;
                    b[nt][0] = Bsm[(kk + tg) * 136 + c];
                    b[nt][1] = Bsm[(kk + tg + 4) * 136 + c];
                }
#pragma unroll
                for (int mt = 0; mt < 2; mt++)
#pragma unroll
                    for (int nt = 0; nt < 4; nt++)
                        mma8(acc[mt][nt], a[mt], b[nt]);
            }
        }
        __syncthreads();
#pragma unroll
        for (int mt = 0; mt < 2; mt++) {
#pragma unroll
            for (int nt = 0; nt < 4; nt++) {
                int r = m0 + wm + mt * 16 + g;
                int gc = half * 128 + wn + nt * 8 + 2 * tg;
                int j = gc >> 1;
                float bm = bil_r[gc], bl = bil_r[gc + 1];
                float mean0 = acc[mt][nt][0] + bm, lv0 = acc[mt][nt][1] + bl;
                float mean1 = acc[mt][nt][2] + bm, lv1 = acc[mt][nt][3] + bl;
                wbuf[(size_t)r * 128 + j] =
                    mean0 + expf(0.5f * lv0) * eps_t[(size_t)r * 128 + j];
                wbuf[(size_t)(r + 8) * 128 + j] =
                    mean1 + expf(0.5f * lv1) * eps_t[(size_t)(r + 8) * 128 + j];
            }
        }
    }
}

// ---------------- fused alpha softmax + mix reduce (wide, from R6) ---------
__global__ __launch_bounds__(256) void reduce_alpha(
    const float* __restrict__ P, const float* __restrict__ z,
    const float* __restrict__ aW, const float* __restrict__ alphau_t,
    float* __restrict__ znext) {
    __shared__ float aWs[128 * 16];
    __shared__ float zsh[2][128];
    __shared__ float sa[2][16];
    const int tid = threadIdx.x;
    const int sub = tid >> 7, lt = tid & 127;
    const int b = blockIdx.x * 2 + sub;
    for (int i = tid; i < 128 * 16; i += 256) aWs[i] = aW[i];
    zsh[sub][lt] = z[(size_t)b * 128 + lt];
    __syncthreads();
    if (lt < 16) {
        float acc = alphau_t[(size_t)b * 16 + lt];
#pragma unroll 8
        for (int k = 0; k < 128; k++) acc += zsh[sub][k] * aWs[k * 16 + lt];
        sa[sub][lt] = acc;
    }
    __syncthreads();
    if (lt < 16) {
        float mx = -1e30f;
#pragma unroll
        for (int q = 0; q < 16; q++) mx = fmaxf(mx, sa[sub][q]);
        float e = expf(sa[sub][lt] - mx);
        zsh[sub][lt] = e;
    }
    __syncthreads();
    if (lt < 16) {
        float s = 0.f;
#pragma unroll
        for (int q = 0; q < 16; q++) s += zsh[sub][q];
        sa[sub][lt] = zsh[sub][lt] / s;
    }
    __syncthreads();
    const float* pb = P + (size_t)b * 2048 + lt;
    float s = 0.f;
#pragma unroll
    for (int i = 0; i < 16; i++) s += sa[sub][i] * pb[i * 128];
    znext[(size_t)b * 128 + lt] = s;
}

// ---------------- host orchestration ----------------
extern "C" void kernel_launch(void* const* d_in, const int* in_sizes, int n_in,
                              void* d_out, int out_size) {
    const float* xs      = (const float*)d_in[0];
    const float* us      = (const float*)d_in[1];
    const float* eps1    = (const float*)d_in[2];
    const float* eps     = (const float*)d_in[3];
    const float* lstm_Wx = (const float*)d_in[4];
    const float* lstm_Wh = (const float*)d_in[5];
    const float* lstm_b  = (const float*)d_in[6];
    const float* init_W1 = (const float*)d_in[7];
    const float* init_b1 = (const float*)d_in[8];
    const float* init_W2 = (const float*)d_in[9];
    const float* init_b2 = (const float*)d_in[10];
    const float* trans_W1= (const float*)d_in[11];
    const float* trans_b1= (const float*)d_in[12];
    const float* trans_W2= (const float*)d_in[13];
    const float* trans_b2= (const float*)d_in[14];
    const float* obs_W1  = (const float*)d_in[15];
    const float* obs_b1  = (const float*)d_in[16];
    const float* obs_W2  = (const float*)d_in[17];
    const float* obs_b2  = (const float*)d_in[18];
    const float* rec_W1  = (const float*)d_in[19];
    const float* rec_b1  = (const float*)d_in[20];
    const float* rec_W2  = (const float*)d_in[21];
    const float* rec_b2  = (const float*)d_in[22];
    const float* alpha_W = (const float*)d_in[23];
    const float* Abank   = (const float*)d_in[24];
    const float* Bbank   = (const float*)d_in[25];
    const float* Cbank   = (const float*)d_in[26];

    float *h0, *h1, *c, *hbuf, *wbuf, *alphaB, *P;
    float *Wil_i, *Wil_r, *bil_i, *bil_r, *Mbig, *Gx, *Rxu, *alphau, *Hobs, *WxP;
    cudaGetSymbolAddress((void**)&h0, g_h0);
    cudaGetSymbolAddress((void**)&h1, g_h1);
    cudaGetSymbolAddress((void**)&c, g_c);
    cudaGetSymbolAddress((void**)&hbuf, g_hbuf);
    cudaGetSymbolAddress((void**)&wbuf, g_wbuf);
    cudaGetSymbolAddress((void**)&alphaB, g_alpha);
    cudaGetSymbolAddress((void**)&P, g_P);
    cudaGetSymbolAddress((void**)&Mbig, g_Mbig);
    cudaGetSymbolAddress((void**)&Wil_i, g_W2il_init);
    cudaGetSymbolAddress((void**)&Wil_r, g_W2il_rec);
    cudaGetSymbolAddress((void**)&bil_i, g_b2il_init);
    cudaGetSymbolAddress((void**)&bil_r, g_b2il_rec);
    cudaGetSymbolAddress((void**)&Gx, g_Gx);
    cudaGetSymbolAddress((void**)&Rxu, g_Rxu);
    cudaGetSymbolAddress((void**)&alphau, g_alphau);
    cudaGetSymbolAddress((void**)&Hobs, g_Hobs);
    cudaGetSymbolAddress((void**)&WxP, g_WxP);

    static cudaStream_t sB;
    static cudaEvent_t evRoot, evPre, eobs[4], evJoin;
    static int inited = 0;
    if (!inited) {
        cudaFuncSetAttribute(recgauss, cudaFuncAttributeMaxDynamicSharedMemorySize,
                             RG_SMEM_FLOATS * 4);
        cudaStreamCreateWithFlags(&sB, cudaStreamNonBlocking);
        cudaEventCreateWithFlags(&evRoot, cudaEventDisableTiming);
        cudaEventCreateWithFlags(&evPre, cudaEventDisableTiming);
        for (int i = 0; i < 4; i++)
            cudaEventCreateWithFlags(&eobs[i], cudaEventDisableTiming);
        cudaEventCreateWithFlags(&evJoin, cudaEventDisableTiming);
        inited = 1;
    }

    float* zs   = (float*)d_out;
    float* xrec = zs + (size_t)TT * BB * LAT;

    cudaMemsetAsync(h0, 0, sizeof(float) * BB * HH);
    cudaMemsetAsync(c, 0, sizeof(float) * BB * HH);
    cudaEventRecord(evRoot, 0);

    // ---- side stream: pre-work independent of the LSTM chain ----
    cudaStreamWaitEvent(sB, evRoot, 0);
    build_mbig<<<(272 * 2048 + 255) / 256, 256, 0, sB>>>(Abank, Bbank, Cbank);
    build_w2il<<<(128 * 256 + 255) / 256, 256, 0, sB>>>(init_W2, init_b2, Wil_i, bil_i);
    build_w2il<<<(128 * 256 + 255) / 256, 256, 0, sB>>>(rec_W2, rec_b2, Wil_r, bil_r);
    alphau_kernel<<<(TM1 * BB + 255) / 256, 256, 0, sB>>>(us, alpha_W);
    tmm<0, true><<<dim3(TM1 * BB / 128, 1), 256, 0, sB>>>(
        xs + (size_t)BB * OBSD, 128, us, 16, nullptr, 0,
        rec_W1 + 128 * 128, rec_b1, nullptr, Rxu, TM1 * BB, 128, 144);
    cudaEventRecord(evPre, sB);

    // ---- main stream: LSTM chain ----
    build_wstack<<<(128 * 512 + 255) / 256, 256>>>(lstm_Wx, lstm_Wh, lstm_b);
    tmm<0, false><<<dim3(TT * BB / 128, 4), 256>>>(
        xs, 128, nullptr, 0, nullptr, 0, WxP, nullptr, nullptr,
        Gx, TT * BB, 512, 128);
    dim3 gLSTM(BB / 128, 4);
    for (int t = 0; t < TT; t++) {
        const float* hin = (t & 1) ? h1 : h0;
        float* hout      = (t & 1) ? h0 : h1;
        lstm_step<<<gLSTM, 256>>>(Gx + (size_t)t * BB * 512, hin, c, hout);
    }
    float* hfin = h0;  // t=63 (odd) wrote h0

    cudaStreamWaitEvent(0, evPre, 0);

    dim3 g1(BB / 128, 1), g2(BB / 128, 2), gMix(BB / 128, 16);
    // init network -> z_0 in zs
    tmm<1, true><<<g1, 256>>>(hfin, 128, nullptr, 0, nullptr, 0,
                              init_W1, init_b1, nullptr, hbuf, BB, 128, 128);
    tmm<2, true><<<g2, 256>>>(hbuf, 128, nullptr, 0, nullptr, 0,
                              Wil_i, bil_i, eps1, wbuf, BB, 256, 128);
    tmm<1, true><<<g1, 256>>>(wbuf, 128, nullptr, 0, nullptr, 0,
                              trans_W1, trans_b1, nullptr, hbuf, BB, 128, 128);
    tmm<0, true><<<g1, 256>>>(hbuf, 128, nullptr, 0, nullptr, 0,
                              trans_W2, trans_b2, nullptr, zs, BB, 128, 128);

    // scan: 3 kernels per step; record obs-chunk readiness events
    for (int t = 0; t < TM1; t++) {
        const float* z = zs + (size_t)t * BB * LAT;
        float* zn      = zs + (size_t)(t + 1) * BB * LAT;
        recgauss<<<32, 256, RG_SMEM_FLOATS * 4>>>(
            z, Rxu + (size_t)t * BB * HH, rec_W1,
            Wil_r, bil_r, eps + (size_t)t * BB * LAT, wbuf);
        tmm<0, false><<<gMix, 256>>>(z, 128, us + (size_t)t * BB * CTRL, 16,
                                     wbuf, 128, Mbig, nullptr, nullptr,
                                     P, BB, 2048, 272);
        reduce_alpha<<<BB / 2, 256>>>(P, z, alpha_W,
                                      alphau + (size_t)t * BB * NMATD, zn);
        if (t == 14) cudaEventRecord(eobs[0], 0);
        if (t == 30) cudaEventRecord(eobs[1], 0);
        if (t == 46) cudaEventRecord(eobs[2], 0);
        if (t == 61) cudaEventRecord(eobs[3], 0);
    }

    // ---- side stream: observation network in 4 chunks, overlapping scan ----
    for (int cidx = 0; cidx < 4; cidx++) {
        int tstart = cidx * 16;
        int nsteps = (cidx < 3) ? 16 : (TM1 - 48);   // 16,16,16,15
        size_t row0 = (size_t)tstart * BB;
        int rows = nsteps * BB;
        cudaStreamWaitEvent(sB, eobs[cidx], 0);
        tmm<1, true><<<dim3(rows / 128, 1), 256, 0, sB>>>(
            zs + row0 * LAT, 128, nullptr, 0, nullptr, 0,
            obs_W1, obs_b1, nullptr, Hobs + row0 * HH, rows, 128, 128);
        tmm<0, true><<<dim3(rows / 128, 1), 256, 0, sB>>>(
            Hobs + row0 * HH, 128, nullptr, 0, nullptr, 0,
            obs_W2, obs_b2, nullptr, xrec + row0 * OBSD, rows, 128, 128);
    }
    cudaEventRecord(evJoin, sB);
    cudaStreamWaitEvent(0, evJoin, 0);
}

// round 14
// speedup vs baseline: 1.3721x; 1.1627x over previous
#include <cuda_runtime.h>
#include <math.h>

#define TT    64
#define BB    2048
#define LAT   128
#define OBSD  128
#define CTRL  16
#define NMATD 16
#define HH    128
#define TM1   (TT - 1)

// ---------------- scratch (no allocation allowed) ----------------
__device__ float g_h0[BB * HH];
__device__ float g_h1[BB * HH];
__device__ float g_c[BB * HH];
__device__ float g_hbuf[BB * HH];
__device__ float g_wbuf[BB * LAT];
__device__ float g_Pzu[BB * NMATD * LAT];       // [z|u] part of P
__device__ float g_Pw[BB * NMATD * LAT];        // w part of P
__device__ float g_WxP[128 * 512];
__device__ float g_WhP[128 * 512];
__device__ float g_bstack[512];
__device__ float g_Mbig[272 * NMATD * LAT];     // rows c in [z|u|w], cols i*128+j
__device__ float g_W2il_init[128 * 256];
__device__ float g_W2il_rec[128 * 256];
__device__ float g_b2il_init[256];
__device__ float g_b2il_rec[256];
__device__ float g_Gx[TT * BB * 512];
__device__ float g_Rxu[TM1 * BB * HH];
__device__ float g_alphau[TM1 * BB * NMATD];
__device__ float g_Hobs[TM1 * BB * HH];

// ---------------- helpers ----------------
__device__ __forceinline__ float tf32r(float x) {
    unsigned u;
    asm("cvt.rna.tf32.f32 %0, %1;" : "=r"(u) : "f"(x));
    return __uint_as_float(u);
}

__device__ __forceinline__ void mma8(float (&c)[4], const float (&a)[4],
                                     const float (&b)[2]) {
    asm volatile(
        "mma.sync.aligned.m16n8k8.row.col.f32.tf32.tf32.f32 "
        "{%0,%1,%2,%3}, {%4,%5,%6,%7}, {%8,%9}, {%0,%1,%2,%3};\n"
        : "+f"(c[0]), "+f"(c[1]), "+f"(c[2]), "+f"(c[3])
        : "r"(__float_as_uint(a[0])), "r"(__float_as_uint(a[1])),
          "r"(__float_as_uint(a[2])), "r"(__float_as_uint(a[3])),
          "r"(__float_as_uint(b[0])), "r"(__float_as_uint(b[1])));
}

// ---------------- weight prep ----------------
__global__ void build_wstack(const float* __restrict__ Wx,
                             const float* __restrict__ Wh,
                             const float* __restrict__ b) {
    int idx = blockIdx.x * blockDim.x + threadIdx.x;
    if (idx < 128 * 512) {
        int row = idx / 512, cp = idx % 512;
        int gate = (cp >> 3) & 3;
        int j = (cp >> 5) * 8 + (cp & 7);
        int orig = gate * 128 + j;
        g_WxP[idx] = Wx[row * 512 + orig];
        g_WhP[idx] = Wh[row * 512 + orig];
    }
    if (idx < 512) {
        int gate = (idx >> 3) & 3;
        int j = (idx >> 5) * 8 + (idx & 7);
        g_bstack[idx] = b[gate * 128 + j];
    }
}

__global__ void build_mbig(const float* __restrict__ A,
                           const float* __restrict__ Bm,
                           const float* __restrict__ C) {
    int idx = blockIdx.x * blockDim.x + threadIdx.x;
    if (idx >= 272 * 2048) return;
    int c = idx / 2048, n = idx % 2048;
    int i = n >> 7, j = n & 127;
    float v;
    if (c < 128)       v = A[i * 128 * 128 + j * 128 + c];
    else if (c < 144)  v = Bm[i * 128 * 16 + j * 16 + (c - 128)];
    else               v = C[i * 128 * 128 + j * 128 + (c - 144)];
    g_Mbig[idx] = v;
}

__global__ void build_w2il(const float* __restrict__ W, const float* __restrict__ b,
                           float* __restrict__ Wil, float* __restrict__ bil) {
    int idx = blockIdx.x * blockDim.x + threadIdx.x;
    if (idx < 128 * 256) {
        int k = idx / 256, cp = idx % 256;
        Wil[idx] = W[k * 256 + (cp & 1) * 128 + (cp >> 1)];
    }
    if (idx < 256) bil[idx] = b[(idx & 1) * 128 + (idx >> 1)];
}

__global__ void alphau_kernel(const float* __restrict__ us,
                              const float* __restrict__ aW) {
    int m = blockIdx.x * blockDim.x + threadIdx.x;
    if (m >= TM1 * BB) return;
    float u[16];
    const float* up = us + (size_t)m * 16;
#pragma unroll
    for (int k = 0; k < 16; k++) u[k] = up[k];
#pragma unroll
    for (int i = 0; i < 16; i++) {
        float s = 0.f;
#pragma unroll
        for (int k = 0; k < 16; k++) s += u[k] * aW[(128 + k) * 16 + i];
        g_alphau[(size_t)m * 16 + i] = s;
    }
}

// ---------------- tf32 tensor GEMM, CTA 128x128, cat3 A operand ------------
template <int ACT, bool BIAS>
__global__ __launch_bounds__(256) void tmm(
    const float* __restrict__ s0, int w0,
    const float* __restrict__ s1, int w1,
    const float* __restrict__ s2, int w2,
    const float* __restrict__ W, const float* __restrict__ bias,
    const float* __restrict__ eps,
    float* __restrict__ out, int M, int N, int K) {
    __shared__ float As[16][136];
    __shared__ float Bs[16][136];
    const int tid = threadIdx.x;
    const int lane = tid & 31, warp = tid >> 5;
    const int m0 = blockIdx.x * 128, n0 = blockIdx.y * 128;
    const int wm = (warp >> 2) * 64, wn = (warp & 3) * 32;
    const int g = lane >> 2, tg = lane & 3;
    float acc[4][4][4];
#pragma unroll
    for (int i = 0; i < 4; i++)
#pragma unroll
        for (int j = 0; j < 4; j++)
#pragma unroll
            for (int q = 0; q < 4; q++) acc[i][j][q] = 0.f;

    const int nch = K >> 4;
    float4 pa[2], pb[2];

    auto gload = [&](int ch) {
        int kb = ch << 4;
        const float* sp; int sw;
        if (kb < w0)           { sp = s0 + kb;            sw = w0; }
        else if (kb < w0 + w1) { sp = s1 + (kb - w0);      sw = w1; }
        else                   { sp = s2 + (kb - w0 - w1); sw = w2; }
#pragma unroll
        for (int i = 0; i < 2; i++) {
            int idx = tid + (i << 8);
            int r = idx >> 2, c4 = (idx & 3) << 2;
            pa[i] = *(const float4*)(sp + (size_t)(m0 + r) * sw + c4);
            int br = idx >> 5, bc4 = (idx & 31) << 2;
            pb[i] = *(const float4*)(W + (size_t)(kb + br) * N + n0 + bc4);
        }
    };
    auto sstore = [&]() {
#pragma unroll
        for (int i = 0; i < 2; i++) {
            int idx = tid + (i << 8);
            int r = idx >> 2, c4 = (idx & 3) << 2;
            As[c4 + 0][r] = tf32r(pa[i].x); As[c4 + 1][r] = tf32r(pa[i].y);
            As[c4 + 2][r] = tf32r(pa[i].z); As[c4 + 3][r] = tf32r(pa[i].w);
            int br = idx >> 5, bc4 = (idx & 31) << 2;
            float4 t;
            t.x = tf32r(pb[i].x); t.y = tf32r(pb[i].y);
            t.z = tf32r(pb[i].z); t.w = tf32r(pb[i].w);
            *(float4*)&Bs[br][bc4] = t;
        }
    };

    gload(0);
    for (int ch = 0; ch < nch; ch++) {
        __syncthreads();
        sstore();
        __syncthreads();
        if (ch + 1 < nch) gload(ch + 1);
#pragma unroll
        for (int kk = 0; kk < 16; kk += 8) {
            float a[4][4], b[4][2];
#pragma unroll
            for (int mt = 0; mt < 4; mt++) {
                int r = wm + mt * 16 + g;
                a[mt][0] = As[kk + tg][r];
                a[mt][1] = As[kk + tg][r + 8];
                a[mt][2] = As[kk + tg + 4][r];
                a[mt][3] = As[kk + tg + 4][r + 8];
            }
#pragma unroll
            for (int nt = 0; nt < 4; nt++) {
                int c = wn + nt * 8 + g;
                b[nt][0] = Bs[kk + tg][c];
                b[nt][1] = Bs[kk + tg + 4][c];
            }
#pragma unroll
            for (int mt = 0; mt < 4; mt++)
#pragma unroll
                for (int nt = 0; nt < 4; nt++)
                    mma8(acc[mt][nt], a[mt], b[nt]);
        }
    }

#pragma unroll
    for (int mt = 0; mt < 4; mt++) {
#pragma unroll
        for (int nt = 0; nt < 4; nt++) {
            int r = m0 + wm + mt * 16 + g;
            int c = n0 + wn + nt * 8 + 2 * tg;
            if (ACT == 2) {
                int j = c >> 1;
                float bm = bias[c], bl = bias[c + 1];
                float mean0 = acc[mt][nt][0] + bm, lv0 = acc[mt][nt][1] + bl;
                float mean1 = acc[mt][nt][2] + bm, lv1 = acc[mt][nt][3] + bl;
                out[(size_t)r * 128 + j] =
                    mean0 + expf(0.5f * lv0) * eps[(size_t)r * 128 + j];
                out[(size_t)(r + 8) * 128 + j] =
                    mean1 + expf(0.5f * lv1) * eps[(size_t)(r + 8) * 128 + j];
            } else {
                float2 v0 = make_float2(acc[mt][nt][0], acc[mt][nt][1]);
                float2 v1 = make_float2(acc[mt][nt][2], acc[mt][nt][3]);
                if (BIAS) {
                    float bx = bias[c], by = bias[c + 1];
                    v0.x += bx; v0.y += by; v1.x += bx; v1.y += by;
                }
                if (ACT == 1) {
                    v0.x = fmaxf(v0.x, 0.f); v0.y = fmaxf(v0.y, 0.f);
                    v1.x = fmaxf(v1.x, 0.f); v1.y = fmaxf(v1.y, 0.f);
                }
                *(float2*)(out + (size_t)r * N + c) = v0;
                *(float2*)(out + (size_t)(r + 8) * N + c) = v1;
            }
        }
    }
}

// ---------------- fused tf32 LSTM step ----------------
__global__ __launch_bounds__(256) void lstm_step(
    const float* __restrict__ gx, const float* __restrict__ hin,
    float* __restrict__ c, float* __restrict__ hout) {
    __shared__ float As[16][136];
    __shared__ float Bs[16][136];
    const int tid = threadIdx.x;
    const int lane = tid & 31, warp = tid >> 5;
    const int m0 = blockIdx.x * 128, n0 = blockIdx.y * 128;
    const int wm = (warp >> 2) * 64, wn = (warp & 3) * 32;
    const int g = lane >> 2, tg = lane & 3;
    float acc[4][4][4];
#pragma unroll
    for (int i = 0; i < 4; i++)
#pragma unroll
        for (int j = 0; j < 4; j++)
#pragma unroll
            for (int q = 0; q < 4; q++) acc[i][j][q] = 0.f;

    float4 pa[2], pb[2];
    auto gload = [&](int ch) {
        int kb = ch << 4;
#pragma unroll
        for (int i = 0; i < 2; i++) {
            int idx = tid + (i << 8);
            int r = idx >> 2, c4 = (idx & 3) << 2;
            pa[i] = *(const float4*)(hin + (size_t)(m0 + r) * 128 + kb + c4);
            int br = idx >> 5, bc4 = (idx & 31) << 2;
            pb[i] = *(const float4*)(g_WhP + (size_t)(kb + br) * 512 + n0 + bc4);
        }
    };
    auto sstore = [&]() {
#pragma unroll
        for (int i = 0; i < 2; i++) {
            int idx = tid + (i << 8);
            int r = idx >> 2, c4 = (idx & 3) << 2;
            As[c4 + 0][r] = tf32r(pa[i].x); As[c4 + 1][r] = tf32r(pa[i].y);
            As[c4 + 2][r] = tf32r(pa[i].z); As[c4 + 3][r] = tf32r(pa[i].w);
            int br = idx >> 5, bc4 = (idx & 31) << 2;
            float4 t;
            t.x = tf32r(pb[i].x); t.y = tf32r(pb[i].y);
            t.z = tf32r(pb[i].z); t.w = tf32r(pb[i].w);
            *(float4*)&Bs[br][bc4] = t;
        }
    };

    gload(0);
    for (int ch = 0; ch < 8; ch++) {
        __syncthreads();
        sstore();
        __syncthreads();
        if (ch + 1 < 8) gload(ch + 1);
#pragma unroll
        for (int kk = 0; kk < 16; kk += 8) {
            float a[4][4], b[4][2];
#pragma unroll
            for (int mt = 0; mt < 4; mt++) {
                int r = wm + mt * 16 + g;
                a[mt][0] = As[kk + tg][r];
                a[mt][1] = As[kk + tg][r + 8];
                a[mt][2] = As[kk + tg + 4][r];
                a[mt][3] = As[kk + tg + 4][r + 8];
            }
#pragma unroll
            for (int nt = 0; nt < 4; nt++) {
                int cc = wn + nt * 8 + g;
                b[nt][0] = Bs[kk + tg][cc];
                b[nt][1] = Bs[kk + tg + 4][cc];
            }
#pragma unroll
            for (int mt = 0; mt < 4; mt++)
#pragma unroll
                for (int nt = 0; nt < 4; nt++)
                    mma8(acc[mt][nt], a[mt], b[nt]);
        }
    }

    const int jbase = ((n0 + wn) >> 5) * 8 + 2 * tg;
    float bs[4][2];
#pragma unroll
    for (int nt = 0; nt < 4; nt++) {
        bs[nt][0] = g_bstack[n0 + wn + nt * 8 + 2 * tg];
        bs[nt][1] = g_bstack[n0 + wn + nt * 8 + 2 * tg + 1];
    }
#pragma unroll
    for (int mt = 0; mt < 4; mt++) {
#pragma unroll
        for (int half = 0; half < 2; half++) {
            int row = m0 + wm + mt * 16 + g + half * 8;
            float2 gxv[4];
#pragma unroll
            for (int nt = 0; nt < 4; nt++)
                gxv[nt] = *(const float2*)(gx + (size_t)row * 512 + n0 + wn + nt * 8 + 2 * tg);
#pragma unroll
            for (int b = 0; b < 2; b++) {
                int q = half * 2 + b;
                float gi = acc[mt][0][q] + bs[0][b] + (b ? gxv[0].y : gxv[0].x);
                float gf = acc[mt][1][q] + bs[1][b] + (b ? gxv[1].y : gxv[1].x);
                float gg = acc[mt][2][q] + bs[2][b] + (b ? gxv[2].y : gxv[2].x);
                float go = acc[mt][3][q] + bs[3][b] + (b ? gxv[3].y : gxv[3].x);
                float si = 1.f / (1.f + expf(-gi));
                float sf = 1.f / (1.f + expf(-gf));
                float so = 1.f / (1.f + expf(-go));
                size_t idx = (size_t)row * 128 + jbase + b;
                float cn = sf * c[idx] + si * tanhf(gg);
                c[idx] = cn;
                hout[idx] = so * tanhf(cn);
            }
        }
    }
}

// ---------------- step_kernel bodies ----------------
// mixzu: 128x128 tile GEMM, K=144 over cat(z[128]|u[16]), out Pzu (N=2048)
__device__ __forceinline__ void mixzu_body(
    float* sm, int bid, const float* __restrict__ z, const float* __restrict__ u,
    const float* __restrict__ M, float* __restrict__ Pzu) {
    float* As = sm;           // [16][136]
    float* Bs = sm + 2176;    // [16][136]
    const int tid = threadIdx.x;
    const int lane = tid & 31, warp = tid >> 5;
    const int m0 = (bid & 15) * 128, n0 = (bid >> 4) * 128;
    const int wm = (warp >> 2) * 64, wn = (warp & 3) * 32;
    const int g = lane >> 2, tg = lane & 3;
    float acc[4][4][4];
#pragma unroll
    for (int i = 0; i < 4; i++)
#pragma unroll
        for (int j = 0; j < 4; j++)
#pragma unroll
            for (int q = 0; q < 4; q++) acc[i][j][q] = 0.f;
    float4 pa[2], pb[2];
    auto gload = [&](int ch) {
        int kb = ch << 4;
        const float* sp; int sw;
        if (kb < 128) { sp = z + kb; sw = 128; }
        else          { sp = u;      sw = 16;  }
#pragma unroll
        for (int i = 0; i < 2; i++) {
            int idx = tid + (i << 8);
            int r = idx >> 2, c4 = (idx & 3) << 2;
            pa[i] = *(const float4*)(sp + (size_t)(m0 + r) * sw + c4);
            int br = idx >> 5, bc4 = (idx & 31) << 2;
            pb[i] = *(const float4*)(M + (size_t)(kb + br) * 2048 + n0 + bc4);
        }
    };
    auto sstore = [&]() {
#pragma unroll
        for (int i = 0; i < 2; i++) {
            int idx = tid + (i << 8);
            int r = idx >> 2, c4 = (idx & 3) << 2;
            As[(c4 + 0) * 136 + r] = tf32r(pa[i].x);
            As[(c4 + 1) * 136 + r] = tf32r(pa[i].y);
            As[(c4 + 2) * 136 + r] = tf32r(pa[i].z);
            As[(c4 + 3) * 136 + r] = tf32r(pa[i].w);
            int br = idx >> 5, bc4 = (idx & 31) << 2;
            float4 t;
            t.x = tf32r(pb[i].x); t.y = tf32r(pb[i].y);
            t.z = tf32r(pb[i].z); t.w = tf32r(pb[i].w);
            *(float4*)&Bs[br * 136 + bc4] = t;
        }
    };
    gload(0);
    for (int ch = 0; ch < 9; ch++) {
        __syncthreads();
        sstore();
        __syncthreads();
        if (ch + 1 < 9) gload(ch + 1);
#pragma unroll
        for (int kk = 0; kk < 16; kk += 8) {
            float a[4][4], b[4][2];
#pragma unroll
            for (int mt = 0; mt < 4; mt++) {
                int r = wm + mt * 16 + g;
                a[mt][0] = As[(kk + tg) * 136 + r];
                a[mt][1] = As[(kk + tg) * 136 + r + 8];
                a[mt][2] = As[(kk + tg + 4) * 136 + r];
                a[mt][3] = As[(kk + tg + 4) * 136 + r + 8];
            }
#pragma unroll
            for (int nt = 0; nt < 4; nt++) {
                int c = wn + nt * 8 + g;
                b[nt][0] = Bs[(kk + tg) * 136 + c];
                b[nt][1] = Bs[(kk + tg + 4) * 136 + c];
            }
#pragma unroll
            for (int mt = 0; mt < 4; mt++)
#pragma unroll
                for (int nt = 0; nt < 4; nt++)
                    mma8(acc[mt][nt], a[mt], b[nt]);
        }
    }
#pragma unroll
    for (int mt = 0; mt < 4; mt++) {
#pragma unroll
        for (int nt = 0; nt < 4; nt++) {
            int r = m0 + wm + mt * 16 + g;
            int c = n0 + wn + nt * 8 + 2 * tg;
            *(float2*)(Pzu + (size_t)r * 2048 + c) =
                make_float2(acc[mt][nt][0], acc[mt][nt][1]);
            *(float2*)(Pzu + (size_t)(r + 8) * 2048 + c) =
                make_float2(acc[mt][nt][2], acc[mt][nt][3]);
        }
    }
}

// recgauss body: rec stage1 + gauss sample, 64-row tile per block
__device__ __forceinline__ void recgauss_body(
    float* sm,
    const float* __restrict__ z, const float* __restrict__ Rxu_t,
    const float* __restrict__ recW1,
    const float* __restrict__ Wil_r, const float* __restrict__ bil_r,
    const float* __restrict__ eps_t, float* __restrict__ wbuf) {
    float* Zs  = sm;                 // [64][132]
    float* Rs  = sm + 8448;          // [64][132]
    float* Bsm = sm + 16896;         // [16][136]
    const int tid = threadIdx.x;
    const int lane = tid & 31, warp = tid >> 5;
    const int m0 = blockIdx.x * 64;
    const int wm = (warp >> 2) * 32, wn = (warp & 3) * 32;
    const int g = lane >> 2, tg = lane & 3;

#pragma unroll
    for (int i = 0; i < 8; i++) {
        int fidx = tid + i * 256;
        int r = fidx >> 5, c4 = (fidx & 31) << 2;
        float4 v = *(const float4*)(z + (size_t)(m0 + r) * 128 + c4);
        *(float4*)&Zs[r * 132 + c4] = v;
    }
    __syncthreads();

    // phase A: Rs = relu(z @ recW1[0:128] + Rxu_t)
    {
        float acc[2][4][4];
#pragma unroll
        for (int i = 0; i < 2; i++)
#pragma unroll
            for (int j = 0; j < 4; j++)
#pragma unroll
                for (int q = 0; q < 4; q++) acc[i][j][q] = 0.f;
        float4 pb[2];
        auto gloadB = [&](int ch) {
#pragma unroll
            for (int i = 0; i < 2; i++) {
                int idx = tid + (i << 8);
                int br = idx >> 5, bc4 = (idx & 31) << 2;
                pb[i] = *(const float4*)(recW1 + (size_t)(ch * 16 + br) * 128 + bc4);
            }
        };
        auto sstoreB = [&]() {
#pragma unroll
            for (int i = 0; i < 2; i++) {
                int idx = tid + (i << 8);
                int br = idx >> 5, bc4 = (idx & 31) << 2;
                float4 t;
                t.x = tf32r(pb[i].x); t.y = tf32r(pb[i].y);
                t.z = tf32r(pb[i].z); t.w = tf32r(pb[i].w);
                *(float4*)&Bsm[br * 136 + bc4] = t;
            }
        };
        gloadB(0);
        for (int ch = 0; ch < 8; ch++) {
            __syncthreads();
            sstoreB();
            __syncthreads();
            if (ch + 1 < 8) gloadB(ch + 1);
            int kb = ch << 4;
#pragma unroll
            for (int kk = 0; kk < 16; kk += 8) {
                float a[2][4], b[4][2];
#pragma unroll
                for (int mt = 0; mt < 2; mt++) {
                    int r = wm + mt * 16 + g;
                    a[mt][0] = tf32r(Zs[r * 132 + kb + kk + tg]);
                    a[mt][1] = tf32r(Zs[(r + 8) * 132 + kb + kk + tg]);
                    a[mt][2] = tf32r(Zs[r * 132 + kb + kk + tg + 4]);
                    a[mt][3] = tf32r(Zs[(r + 8) * 132 + kb + kk + tg + 4]);
                }
#pragma unroll
                for (int nt = 0; nt < 4; nt++) {
                    int c = wn + nt * 8 + g;
                    b[nt][0] = Bsm[(kk + tg) * 136 + c];
                    b[nt][1] = Bsm[(kk + tg + 4) * 136 + c];
                }
#pragma unroll
                for (int mt = 0; mt < 2; mt++)
#pragma unroll
                    for (int nt = 0; nt < 4; nt++)
                        mma8(acc[mt][nt], a[mt], b[nt]);
            }
        }
        __syncthreads();
#pragma unroll
        for (int mt = 0; mt < 2; mt++) {
#pragma unroll
            for (int nt = 0; nt < 4; nt++) {
                int r = wm + mt * 16 + g;
                int c = wn + nt * 8 + 2 * tg;
                float2 x0 = *(const float2*)(Rxu_t + (size_t)(m0 + r) * 128 + c);
                float2 x1 = *(const float2*)(Rxu_t + (size_t)(m0 + r + 8) * 128 + c);
                Rs[r * 132 + c]           = fmaxf(acc[mt][nt][0] + x0.x, 0.f);
                Rs[r * 132 + c + 1]       = fmaxf(acc[mt][nt][1] + x0.y, 0.f);
                Rs[(r + 8) * 132 + c]     = fmaxf(acc[mt][nt][2] + x1.x, 0.f);
                Rs[(r + 8) * 132 + c + 1] = fmaxf(acc[mt][nt][3] + x1.y, 0.f);
            }
        }
    }
    __syncthreads();

    // phase B: wbuf = gauss(Rs @ Wil_r + bil_r), two n-halves
    for (int half = 0; half < 2; half++) {
        float acc[2][4][4];
#pragma unroll
        for (int i = 0; i < 2; i++)
#pragma unroll
            for (int j = 0; j < 4; j++)
#pragma unroll
                for (int q = 0; q < 4; q++) acc[i][j][q] = 0.f;
        float4 pb[2];
        auto gloadB = [&](int ch) {
#pragma unroll
            for (int i = 0; i < 2; i++) {
                int idx = tid + (i << 8);
                int br = idx >> 5, bc4 = (idx & 31) << 2;
                pb[i] = *(const float4*)(Wil_r + (size_t)(ch * 16 + br) * 256 +
                                         half * 128 + bc4);
            }
        };
        auto sstoreB = [&]() {
#pragma unroll
            for (int i = 0; i < 2; i++) {
                int idx = tid + (i << 8);
                int br = idx >> 5, bc4 = (idx & 31) << 2;
                float4 t;
                t.x = tf32r(pb[i].x); t.y = tf32r(pb[i].y);
                t.z = tf32r(pb[i].z); t.w = tf32r(pb[i].w);
                *(float4*)&Bsm[br * 136 + bc4] = t;
            }
        };
        gloadB(0);
        for (int ch = 0; ch < 8; ch++) {
            __syncthreads();
            sstoreB();
            __syncthreads();
            if (ch + 1 < 8) gloadB(ch + 1);
            int kb = ch << 4;
#pragma unroll
            for (int kk = 0; kk < 16; kk += 8) {
                float a[2][4], b[4][2];
#pragma unroll
                for (int mt = 0; mt < 2; mt++) {
                    int r = wm + mt * 16 + g;
                    a[mt][0] = tf32r(Rs[r * 132 + kb + kk + tg]);
                    a[mt][1] = tf32r(Rs[(r + 8) * 132 + kb + kk + tg]);
                    a[mt][2] = tf32r(Rs[r * 132 + kb + kk + tg + 4]);
                    a[mt][3] = tf32r(Rs[(r + 8) * 132 + kb + kk + tg + 4]);
                }
#pragma unroll
                for (int nt = 0; nt < 4; nt++) {
                    int c = wn + nt * 8 + g;
                    b[nt][0] = Bsm[(kk + tg) * 136 + c];
                    b[nt][1] = Bsm[(kk + tg + 4) * 136 + c];
                }
#pragma unroll
                for (int mt = 0; mt < 2; mt++)
#pragma unroll
                    for (int nt = 0; nt < 4; nt++)
                        mma8(acc[mt][nt], a[mt], b[nt]);
            }
        }
        __syncthreads();
#pragma unroll
        for (int mt = 0; mt < 2; mt++) {
#pragma unroll
            for (int nt = 0; nt < 4; nt++) {
                int r = m0 + wm + mt * 16 + g;
                int gc = half * 128 + wn + nt * 8 + 2 * tg;
                int j = gc >> 1;
                float bm = bil_r[gc], bl = bil_r[gc + 1];
                float mean0 = acc[mt][nt][0] + bm, lv0 = acc[mt][nt][1] + bl;
                float mean1 = acc[mt][nt][2] + bm, lv1 = acc[mt][nt][3] + bl;
                wbuf[(size_t)r * 128 + j] =
                    mean0 + expf(0.5f * lv0) * eps_t[(size_t)r * 128 + j];
                wbuf[(size_t)(r + 8) * 128 + j] =
                    mean1 + expf(0.5f * lv1) * eps_t[(size_t)(r + 8) * 128 + j];
            }
        }
    }
}

// step_kernel: blocks 0..31 recgauss; blocks 32..287 mixzu (Pzu)
#define RG_SMEM_FLOATS (8448 + 8448 + 2176)
__global__ __launch_bounds__(256) void step_kernel(
    const float* __restrict__ z, const float* __restrict__ u_t,
    const float* __restrict__ Rxu_t, const float* __restrict__ recW1,
    const float* __restrict__ Wil_r, const float* __restrict__ bil_r,
    const float* __restrict__ eps_t, const float* __restrict__ Mbig,
    float* __restrict__ wbuf, float* __restrict__ Pzu) {
    extern __shared__ float sm[];
    if (blockIdx.x >= 32) {
        mixzu_body(sm, blockIdx.x - 32, z, u_t, Mbig, Pzu);
        return;
    }
    recgauss_body(sm, z, Rxu_t, recW1, Wil_r, bil_r, eps_t, wbuf);
}

// ---------------- fused alpha softmax + split-P mix reduce -----------------
__global__ __launch_bounds__(256) void reduce_alpha2(
    const float* __restrict__ Pzu, const float* __restrict__ Pw,
    const float* __restrict__ z,
    const float* __restrict__ aW, const float* __restrict__ alphau_t,
    float* __restrict__ znext) {
    __shared__ float aWs[128 * 16];
    __shared__ float zsh[2][128];
    __shared__ float sa[2][16];
    const int tid = threadIdx.x;
    const int sub = tid >> 7, lt = tid & 127;
    const int b = blockIdx.x * 2 + sub;
    for (int i = tid; i < 128 * 16; i += 256) aWs[i] = aW[i];
    zsh[sub][lt] = z[(size_t)b * 128 + lt];
    __syncthreads();
    if (lt < 16) {
        float acc = alphau_t[(size_t)b * 16 + lt];
#pragma unroll 8
        for (int k = 0; k < 128; k++) acc += zsh[sub][k] * aWs[k * 16 + lt];
        sa[sub][lt] = acc;
    }
    __syncthreads();
    if (lt < 16) {
        float mx = -1e30f;
#pragma unroll
        for (int q = 0; q < 16; q++) mx = fmaxf(mx, sa[sub][q]);
        float e = expf(sa[sub][lt] - mx);
        zsh[sub][lt] = e;
    }
    __syncthreads();
    if (lt < 16) {
        float s = 0.f;
#pragma unroll
        for (int q = 0; q < 16; q++) s += zsh[sub][q];
        sa[sub][lt] = zsh[sub][lt] / s;
    }
    __syncthreads();
    const float* pz = Pzu + (size_t)b * 2048 + lt;
    const float* pw = Pw + (size_t)b * 2048 + lt;
    float s = 0.f;
#pragma unroll
    for (int i = 0; i < 16; i++)
        s += sa[sub][i] * (pz[i * 128] + pw[i * 128]);
    znext[(size_t)b * 128 + lt] = s;
}

// ---------------- host orchestration ----------------
extern "C" void kernel_launch(void* const* d_in, const int* in_sizes, int n_in,
                              void* d_out, int out_size) {
    const float* xs      = (const float*)d_in[0];
    const float* us      = (const float*)d_in[1];
    const float* eps1    = (const float*)d_in[2];
    const float* eps     = (const float*)d_in[3];
    const float* lstm_Wx = (const float*)d_in[4];
    const float* lstm_Wh = (const float*)d_in[5];
    const float* lstm_b  = (const float*)d_in[6];
    const float* init_W1 = (const float*)d_in[7];
    const float* init_b1 = (const float*)d_in[8];
    const float* init_W2 = (const float*)d_in[9];
    const float* init_b2 = (const float*)d_in[10];
    const float* trans_W1= (const float*)d_in[11];
    const float* trans_b1= (const float*)d_in[12];
    const float* trans_W2= (const float*)d_in[13];
    const float* trans_b2= (const float*)d_in[14];
    const float* obs_W1  = (const float*)d_in[15];
    const float* obs_b1  = (const float*)d_in[16];
    const float* obs_W2  = (const float*)d_in[17];
    const float* obs_b2  = (const float*)d_in[18];
    const float* rec_W1  = (const float*)d_in[19];
    const float* rec_b1  = (const float*)d_in[20];
    const float* rec_W2  = (const float*)d_in[21];
    const float* rec_b2  = (const float*)d_in[22];
    const float* alpha_W = (const float*)d_in[23];
    const float* Abank   = (const float*)d_in[24];
    const float* Bbank   = (const float*)d_in[25];
    const float* Cbank   = (const float*)d_in[26];

    float *h0, *h1, *c, *hbuf, *wbuf, *Pzu, *Pw;
    float *Wil_i, *Wil_r, *bil_i, *bil_r, *Mbig, *Gx, *Rxu, *alphau, *Hobs, *WxP;
    cudaGetSymbolAddress((void**)&h0, g_h0);
    cudaGetSymbolAddress((void**)&h1, g_h1);
    cudaGetSymbolAddress((void**)&c, g_c);
    cudaGetSymbolAddress((void**)&hbuf, g_hbuf);
    cudaGetSymbolAddress((void**)&wbuf, g_wbuf);
    cudaGetSymbolAddress((void**)&Pzu, g_Pzu);
    cudaGetSymbolAddress((void**)&Pw, g_Pw);
    cudaGetSymbolAddress((void**)&Mbig, g_Mbig);
    cudaGetSymbolAddress((void**)&Wil_i, g_W2il_init);
    cudaGetSymbolAddress((void**)&Wil_r, g_W2il_rec);
    cudaGetSymbolAddress((void**)&bil_i, g_b2il_init);
    cudaGetSymbolAddress((void**)&bil_r, g_b2il_rec);
    cudaGetSymbolAddress((void**)&Gx, g_Gx);
    cudaGetSymbolAddress((void**)&Rxu, g_Rxu);
    cudaGetSymbolAddress((void**)&alphau, g_alphau);
    cudaGetSymbolAddress((void**)&Hobs, g_Hobs);
    cudaGetSymbolAddress((void**)&WxP, g_WxP);

    static cudaStream_t sB;
    static cudaEvent_t evRoot, evPre, eobs[4], evJoin;
    static int inited = 0;
    if (!inited) {
        cudaFuncSetAttribute(step_kernel, cudaFuncAttributeMaxDynamicSharedMemorySize,
                             RG_SMEM_FLOATS * 4);
        cudaStreamCreateWithFlags(&sB, cudaStreamNonBlocking);
        cudaEventCreateWithFlags(&evRoot, cudaEventDisableTiming);
        cudaEventCreateWithFlags(&evPre, cudaEventDisableTiming);
        for (int i = 0; i < 4; i++)
            cudaEventCreateWithFlags(&eobs[i], cudaEventDisableTiming);
        cudaEventCreateWithFlags(&evJoin, cudaEventDisableTiming);
        inited = 1;
    }

    float* zs   = (float*)d_out;
    float* xrec = zs + (size_t)TT * BB * LAT;

    cudaMemsetAsync(h0, 0, sizeof(float) * BB * HH);
    cudaMemsetAsync(c, 0, sizeof(float) * BB * HH);
    cudaEventRecord(evRoot, 0);

    // ---- side stream B: pre-work independent of the LSTM chain ----
    cudaStreamWaitEvent(sB, evRoot, 0);
    build_mbig<<<(272 * 2048 + 255) / 256, 256, 0, sB>>>(Abank, Bbank, Cbank);
    build_w2il<<<(128 * 256 + 255) / 256, 256, 0, sB>>>(init_W2, init_b2, Wil_i, bil_i);
    build_w2il<<<(128 * 256 + 255) / 256, 256, 0, sB>>>(rec_W2, rec_b2, Wil_r, bil_r);
    alphau_kernel<<<(TM1 * BB + 255) / 256, 256, 0, sB>>>(us, alpha_W);
    tmm<0, true><<<dim3(TM1 * BB / 128, 1), 256, 0, sB>>>(
        xs + (size_t)BB * OBSD, 128, us, 16, nullptr, 0,
        rec_W1 + 128 * 128, rec_b1, nullptr, Rxu, TM1 * BB, 128, 144);
    cudaEventRecord(evPre, sB);

    // ---- main stream: LSTM chain ----
    build_wstack<<<(128 * 512 + 255) / 256, 256>>>(lstm_Wx, lstm_Wh, lstm_b);
    tmm<0, false><<<dim3(TT * BB / 128, 4), 256>>>(
        xs, 128, nullptr, 0, nullptr, 0, WxP, nullptr, nullptr,
        Gx, TT * BB, 512, 128);
    dim3 gLSTM(BB / 128, 4);
    for (int t = 0; t < TT; t++) {
        const float* hin = (t & 1) ? h1 : h0;
        float* hout      = (t & 1) ? h0 : h1;
        lstm_step<<<gLSTM, 256>>>(Gx + (size_t)t * BB * 512, hin, c, hout);
    }
    float* hfin = h0;  // t=63 (odd) wrote h0

    cudaStreamWaitEvent(0, evPre, 0);

    dim3 g1(BB / 128, 1), g2(BB / 128, 2), gMix(BB / 128, 16);
    // init network -> z_0 in zs
    tmm<1, true><<<g1, 256>>>(hfin, 128, nullptr, 0, nullptr, 0,
                              init_W1, init_b1, nullptr, hbuf, BB, 128, 128);
    tmm<2, true><<<g2, 256>>>(hbuf, 128, nullptr, 0, nullptr, 0,
                              Wil_i, bil_i, eps1, wbuf, BB, 256, 128);
    tmm<1, true><<<g1, 256>>>(wbuf, 128, nullptr, 0, nullptr, 0,
                              trans_W1, trans_b1, nullptr, hbuf, BB, 128, 128);
    tmm<0, true><<<g1, 256>>>(hbuf, 128, nullptr, 0, nullptr, 0,
                              trans_W2, trans_b2, nullptr, zs, BB, 128, 128);

    // scan: 3 kernels per step, all on main stream (no cross-stream sync)
    for (int t = 0; t < TM1; t++) {
        const float* z = zs + (size_t)t * BB * LAT;
        float* zn      = zs + (size_t)(t + 1) * BB * LAT;
        step_kernel<<<288, 256, RG_SMEM_FLOATS * 4>>>(
            z, us + (size_t)t * BB * CTRL,
            Rxu + (size_t)t * BB * HH, rec_W1,
            Wil_r, bil_r, eps + (size_t)t * BB * LAT,
            Mbig, wbuf, Pzu);
        tmm<0, false><<<gMix, 256>>>(
            wbuf, 128, nullptr, 0, nullptr, 0,
            Mbig + 144 * 2048, nullptr, nullptr, Pw, BB, 2048, 128);
        reduce_alpha2<<<BB / 2, 256>>>(Pzu, Pw, z, alpha_W,
                                       alphau + (size_t)t * BB * NMATD, zn);
        if (t == 14) cudaEventRecord(eobs[0], 0);
        if (t == 30) cudaEventRecord(eobs[1], 0);
        if (t == 46) cudaEventRecord(eobs[2], 0);
        if (t == 61) cudaEventRecord(eobs[3], 0);
    }

    // ---- side stream B: observation network in 4 chunks, overlapping scan ----
    for (int cidx = 0; cidx < 4; cidx++) {
        int tstart = cidx * 16;
        int nsteps = (cidx < 3) ? 16 : (TM1 - 48);   // 16,16,16,15
        size_t row0 = (size_t)tstart * BB;
        int rows = nsteps * BB;
        cudaStreamWaitEvent(sB, eobs[cidx], 0);
        tmm<1, true><<<dim3(rows / 128, 1), 256, 0, sB>>>(
            zs + row0 * LAT, 128, nullptr, 0, nullptr, 0,
            obs_W1, obs_b1, nullptr, Hobs + row0 * HH, rows, 128, 128);
        tmm<0, true><<<dim3(rows / 128, 1), 256, 0, sB>>>(
            Hobs + row0 * HH, 128, nullptr, 0, nullptr, 0,
            obs_W2, obs_b2, nullptr, xrec + row0 * OBSD, rows, 128, 128);
    }
    cudaEventRecord(evJoin, sB);
    cudaStreamWaitEvent(0, evJoin, 0);
}